// round 4
// baseline (speedup 1.0000x reference)
#include <cuda_runtime.h>
#include <cstdint>

#define BB 4
#define SS 2048
#define DD 1024
#define HH 16
#define DK 64
#define M_TOT (BB*SS)   // 8192

// Scratch (allocation-free rule: __device__ globals)
__device__ float g_Q[BB*HH*SS*DK];
__device__ float g_K[BB*HH*SS*DK];
__device__ float g_V[BB*HH*SS*DK];
__device__ float g_Ct[(size_t)M_TOT*DD];

// ---------------------------------------------------------------------------
// helpers
// ---------------------------------------------------------------------------
__device__ __forceinline__ uint32_t f2tf32(float f) {
    uint32_t r;
    asm("cvt.rna.tf32.f32 %0, %1;" : "=r"(r) : "f"(f));
    return r;
}

__device__ __forceinline__ float fast_ex2(float x) {
    float y;
    asm("ex2.approx.ftz.f32 %0, %1;" : "=f"(y) : "f"(x));
    return y;
}

__device__ __forceinline__ void mma_tf32(float* c, const uint32_t* a, uint32_t b0, uint32_t b1) {
    asm volatile(
        "mma.sync.aligned.m16n8k8.row.col.f32.tf32.tf32.f32 "
        "{%0,%1,%2,%3}, {%4,%5,%6,%7}, {%8,%9}, {%0,%1,%2,%3};"
        : "+f"(c[0]), "+f"(c[1]), "+f"(c[2]), "+f"(c[3])
        : "r"(a[0]), "r"(a[1]), "r"(a[2]), "r"(a[3]), "r"(b0), "r"(b1));
}

// ---------------------------------------------------------------------------
// QKV projection GEMM: block 128x64, BK=32, 256 threads, warp tile 32x32.
// ---------------------------------------------------------------------------
#define AP2 36   // A pitch (32 + 4): conflict-free scalar A-frag reads
#define BP2 72   // B pitch (64 + 8): conflict-free scalar B-frag reads

__global__ __launch_bounds__(256, 2) void qkv_gemm_t(
    const float* __restrict__ x,
    const float* __restrict__ Wq,
    const float* __restrict__ Wk,
    const float* __restrict__ Wv)
{
    __shared__ uint32_t As[128 * AP2];
    __shared__ uint32_t Bs[32 * BP2];

    const int m0 = blockIdx.x * 128;
    const int h  = blockIdx.y;
    const int z  = blockIdx.z;
    const float* W = (z == 0) ? Wq : (z == 1) ? Wk : Wv;
    float* Cout    = (z == 0) ? g_Q : (z == 1) ? g_K : g_V;
    const float* Wh = W + (size_t)h * DD * DK;

    const int tid  = threadIdx.x;
    const int warp = tid >> 5;
    const int lane = tid & 31;
    const int g    = lane >> 2;
    const int tig  = lane & 3;
    const int wm   = (warp & 3) * 32;
    const int wn   = (warp >> 2) * 32;

    // A loader: row = tid>>1 (0..127), 16 k's at (tid&1)*16
    const int ar = tid >> 1;
    const int ac = (tid & 1) * 16;
    // B loader: k row = tid>>3 (0..31), 8 n's at (tid&7)*8
    const int bk = tid >> 3;
    const int bn = (tid & 7) * 8;

    float acc[2][4][4];
    #pragma unroll
    for (int i = 0; i < 2; ++i)
        #pragma unroll
        for (int j = 0; j < 4; ++j)
            #pragma unroll
            for (int l = 0; l < 4; ++l) acc[i][j][l] = 0.f;

    float4 av[4], bv[2];
    #pragma unroll
    for (int j = 0; j < 4; ++j)
        av[j] = *reinterpret_cast<const float4*>(&x[(size_t)(m0 + ar) * DD + ac + 4 * j]);
    #pragma unroll
    for (int j = 0; j < 2; ++j)
        bv[j] = *reinterpret_cast<const float4*>(&Wh[(size_t)bk * DK + bn + 4 * j]);

    for (int k0 = 0; k0 < DD; k0 += 32) {
        #pragma unroll
        for (int j = 0; j < 4; ++j) {
            uint4 t;
            t.x = f2tf32(av[j].x); t.y = f2tf32(av[j].y);
            t.z = f2tf32(av[j].z); t.w = f2tf32(av[j].w);
            *reinterpret_cast<uint4*>(&As[ar * AP2 + ac + 4 * j]) = t;
        }
        #pragma unroll
        for (int j = 0; j < 2; ++j) {
            uint4 t;
            t.x = f2tf32(bv[j].x); t.y = f2tf32(bv[j].y);
            t.z = f2tf32(bv[j].z); t.w = f2tf32(bv[j].w);
            *reinterpret_cast<uint4*>(&Bs[bk * BP2 + bn + 4 * j]) = t;
        }
        __syncthreads();

        if (k0 + 32 < DD) {
            #pragma unroll
            for (int j = 0; j < 4; ++j)
                av[j] = *reinterpret_cast<const float4*>(&x[(size_t)(m0 + ar) * DD + k0 + 32 + ac + 4 * j]);
            #pragma unroll
            for (int j = 0; j < 2; ++j)
                bv[j] = *reinterpret_cast<const float4*>(&Wh[(size_t)(k0 + 32 + bk) * DK + bn + 4 * j]);
        }

        #pragma unroll
        for (int kc = 0; kc < 4; ++kc) {
            uint32_t af[2][4];
            #pragma unroll
            for (int mt = 0; mt < 2; ++mt) {
                const int rb = wm + mt * 16;
                af[mt][0] = As[(rb + g)     * AP2 + kc * 8 + tig];
                af[mt][1] = As[(rb + g + 8) * AP2 + kc * 8 + tig];
                af[mt][2] = As[(rb + g)     * AP2 + kc * 8 + tig + 4];
                af[mt][3] = As[(rb + g + 8) * AP2 + kc * 8 + tig + 4];
            }
            #pragma unroll
            for (int nt = 0; nt < 4; ++nt) {
                uint32_t b0 = Bs[(kc * 8 + tig)     * BP2 + wn + nt * 8 + g];
                uint32_t b1 = Bs[(kc * 8 + tig + 4) * BP2 + wn + nt * 8 + g];
                #pragma unroll
                for (int mt = 0; mt < 2; ++mt)
                    mma_tf32(acc[mt][nt], af[mt], b0, b1);
            }
        }
        __syncthreads();
    }

    // Epilogue: write [B,H,S,64]
    #pragma unroll
    for (int mt = 0; mt < 2; ++mt) {
        #pragma unroll
        for (int nt = 0; nt < 4; ++nt) {
            const int col = wn + nt * 8 + 2 * tig;
            #pragma unroll
            for (int rh = 0; rh < 2; ++rh) {
                const int m = m0 + wm + mt * 16 + g + rh * 8;
                const int b = m >> 11;
                const int s = m & 2047;
                float2 v = make_float2(acc[mt][nt][rh * 2], acc[mt][nt][rh * 2 + 1]);
                *reinterpret_cast<float2*>(
                    &Cout[(((size_t)(b * HH + h)) * SS + s) * DK + col]) = v;
            }
        }
    }
}

// ---------------------------------------------------------------------------
// Output projection GEMM: same structure, N-tile from Wo.
// ---------------------------------------------------------------------------
__global__ __launch_bounds__(256, 2) void out_gemm_t(
    const float* __restrict__ Wo, float* __restrict__ out)
{
    __shared__ uint32_t As[128 * AP2];
    __shared__ uint32_t Bs[32 * BP2];

    const int m0 = blockIdx.x * 128;
    const int n0 = blockIdx.y * 64;

    const int tid  = threadIdx.x;
    const int warp = tid >> 5;
    const int lane = tid & 31;
    const int g    = lane >> 2;
    const int tig  = lane & 3;
    const int wm   = (warp & 3) * 32;
    const int wn   = (warp >> 2) * 32;

    const int ar = tid >> 1;
    const int ac = (tid & 1) * 16;
    const int bk = tid >> 3;
    const int bn = (tid & 7) * 8;

    float acc[2][4][4];
    #pragma unroll
    for (int i = 0; i < 2; ++i)
        #pragma unroll
        for (int j = 0; j < 4; ++j)
            #pragma unroll
            for (int l = 0; l < 4; ++l) acc[i][j][l] = 0.f;

    float4 av[4], bv[2];
    #pragma unroll
    for (int j = 0; j < 4; ++j)
        av[j] = *reinterpret_cast<const float4*>(&g_Ct[(size_t)(m0 + ar) * DD + ac + 4 * j]);
    #pragma unroll
    for (int j = 0; j < 2; ++j)
        bv[j] = *reinterpret_cast<const float4*>(&Wo[(size_t)bk * DD + n0 + bn + 4 * j]);

    for (int k0 = 0; k0 < DD; k0 += 32) {
        #pragma unroll
        for (int j = 0; j < 4; ++j) {
            uint4 t;
            t.x = f2tf32(av[j].x); t.y = f2tf32(av[j].y);
            t.z = f2tf32(av[j].z); t.w = f2tf32(av[j].w);
            *reinterpret_cast<uint4*>(&As[ar * AP2 + ac + 4 * j]) = t;
        }
        #pragma unroll
        for (int j = 0; j < 2; ++j) {
            uint4 t;
            t.x = f2tf32(bv[j].x); t.y = f2tf32(bv[j].y);
            t.z = f2tf32(bv[j].z); t.w = f2tf32(bv[j].w);
            *reinterpret_cast<uint4*>(&Bs[bk * BP2 + bn + 4 * j]) = t;
        }
        __syncthreads();

        if (k0 + 32 < DD) {
            #pragma unroll
            for (int j = 0; j < 4; ++j)
                av[j] = *reinterpret_cast<const float4*>(&g_Ct[(size_t)(m0 + ar) * DD + k0 + 32 + ac + 4 * j]);
            #pragma unroll
            for (int j = 0; j < 2; ++j)
                bv[j] = *reinterpret_cast<const float4*>(&Wo[(size_t)(k0 + 32 + bk) * DD + n0 + bn + 4 * j]);
        }

        #pragma unroll
        for (int kc = 0; kc < 4; ++kc) {
            uint32_t af[2][4];
            #pragma unroll
            for (int mt = 0; mt < 2; ++mt) {
                const int rb = wm + mt * 16;
                af[mt][0] = As[(rb + g)     * AP2 + kc * 8 + tig];
                af[mt][1] = As[(rb + g + 8) * AP2 + kc * 8 + tig];
                af[mt][2] = As[(rb + g)     * AP2 + kc * 8 + tig + 4];
                af[mt][3] = As[(rb + g + 8) * AP2 + kc * 8 + tig + 4];
            }
            #pragma unroll
            for (int nt = 0; nt < 4; ++nt) {
                uint32_t b0 = Bs[(kc * 8 + tig)     * BP2 + wn + nt * 8 + g];
                uint32_t b1 = Bs[(kc * 8 + tig + 4) * BP2 + wn + nt * 8 + g];
                #pragma unroll
                for (int mt = 0; mt < 2; ++mt)
                    mma_tf32(acc[mt][nt], af[mt], b0, b1);
            }
        }
        __syncthreads();
    }

    #pragma unroll
    for (int mt = 0; mt < 2; ++mt) {
        #pragma unroll
        for (int nt = 0; nt < 4; ++nt) {
            const int col = n0 + wn + nt * 8 + 2 * tig;
            #pragma unroll
            for (int rh = 0; rh < 2; ++rh) {
                const int m = m0 + wm + mt * 16 + g + rh * 8;
                float2 v = make_float2(acc[mt][nt][rh * 2], acc[mt][nt][rh * 2 + 1]);
                *reinterpret_cast<float2*>(&out[(size_t)m * DD + col]) = v;
            }
        }
    }
}

// ---------------------------------------------------------------------------
// Flash attention (mma.sync tf32, high-occupancy):
//   CTA = 128 q-rows of one (b,h); 256 threads / 8 warps; warp = 16 q rows.
//   K  stored [s][d-interleaved]  (pairs (d, d+4) adjacent)  -> B frags = LDS.64
//   V  stored transposed [d][s-interleaved]                  -> B frags = LDS.64
//   P  stored [q][s] pitch 68 (warp-local rows, __syncwarp only)
// ---------------------------------------------------------------------------
#define KPITCH 72
#define PPITCH 68
#define KS_OFF 0                        // 64*72*4  = 18432
#define VT_OFF 18432                    // 64*72*4  = 18432
#define PQ_OFF 36864                    // 128*68*4 = 34816
#define FA_SMEM 71680

__global__ __launch_bounds__(256, 2) void flash_attn_t()
{
    extern __shared__ char smem[];
    uint32_t* Ks = reinterpret_cast<uint32_t*>(smem + KS_OFF);
    uint32_t* Vt = reinterpret_cast<uint32_t*>(smem + VT_OFF);
    uint32_t* PQ = reinterpret_cast<uint32_t*>(smem + PQ_OFF);

    const int tid  = threadIdx.x;
    const int w    = tid >> 5;
    const int lane = tid & 31;
    const int g    = lane >> 2;
    const int tig  = lane & 3;
    const int wr   = w * 16;

    const int q0 = blockIdx.x * 128;
    const int bh = blockIdx.y;
    const float* Qp = g_Q + (size_t)bh * SS * DK;
    const float* Kp = g_K + (size_t)bh * SS * DK;
    const float* Vp = g_V + (size_t)bh * SS * DK;

    // ---- stage Q (scaled by 0.125*log2e) into PQ, natural layout ----
    {
        const float QSC = 0.125f * 1.4426950408889634f;
        const int row = tid >> 1;
        const int dh  = (tid & 1) * 32;
        const float4* src = reinterpret_cast<const float4*>(Qp + (size_t)(q0 + row) * DK + dh);
        #pragma unroll
        for (int j = 0; j < 8; ++j) {
            float4 v = src[j];
            uint4 t;
            t.x = f2tf32(v.x * QSC); t.y = f2tf32(v.y * QSC);
            t.z = f2tf32(v.z * QSC); t.w = f2tf32(v.w * QSC);
            *reinterpret_cast<uint4*>(&PQ[row * PPITCH + dh + 4 * j]) = t;
        }
    }
    __syncthreads();

    // A-fragments of Q (warp-local rows; PQ rows wr..wr+15 also used for P later)
    uint32_t qf[8][4];
    #pragma unroll
    for (int kc = 0; kc < 8; ++kc) {
        qf[kc][0] = PQ[(wr + g)     * PPITCH + kc * 8 + tig];
        qf[kc][1] = PQ[(wr + g + 8) * PPITCH + kc * 8 + tig];
        qf[kc][2] = PQ[(wr + g)     * PPITCH + kc * 8 + tig + 4];
        qf[kc][3] = PQ[(wr + g + 8) * PPITCH + kc * 8 + tig + 4];
    }

    float of[8][4];
    #pragma unroll
    for (int nt = 0; nt < 8; ++nt)
        #pragma unroll
        for (int i = 0; i < 4; ++i) of[nt][i] = 0.f;
    float mA = -1e30f, mB = -1e30f, lA = 0.f, lB = 0.f;

    // staging mapping: s = tid>>2 (0..63), dq = (tid&3)*16
    const int sr = tid >> 2;
    const int dq = (tid & 3) * 16;
    const int jp = (sr & ~7) + 2 * (sr & 3) + ((sr >> 2) & 1);   // interleaved s-pos

    for (int kt = 0; kt < SS; kt += 64) {
        __syncthreads();   // previous tile's Ks/Vt reads complete

        // ---- stage K (interleaved d) and V^T (interleaved s) ----
        {
            const float4* ksrc = reinterpret_cast<const float4*>(Kp + (size_t)(kt + sr) * DK + dq);
            const float4* vsrc = reinterpret_cast<const float4*>(Vp + (size_t)(kt + sr) * DK + dq);
            #pragma unroll
            for (int j = 0; j < 4; ++j) {
                float4 kv = ksrc[j];
                float4 vv = vsrc[j];
                const int d0 = dq + 4 * j;
                const int kb = sr * KPITCH + (d0 & ~7) + ((d0 >> 2) & 1);
                Ks[kb + 0] = f2tf32(kv.x);
                Ks[kb + 2] = f2tf32(kv.y);
                Ks[kb + 4] = f2tf32(kv.z);
                Ks[kb + 6] = f2tf32(kv.w);
                Vt[(d0 + 0) * KPITCH + jp] = f2tf32(vv.x);
                Vt[(d0 + 1) * KPITCH + jp] = f2tf32(vv.y);
                Vt[(d0 + 2) * KPITCH + jp] = f2tf32(vv.z);
                Vt[(d0 + 3) * KPITCH + jp] = f2tf32(vv.w);
            }
        }
        __syncthreads();

        // ---- S = Q K^T (B frags via LDS.64) ----
        float sf[8][4];
        #pragma unroll
        for (int nt = 0; nt < 8; ++nt) {
            sf[nt][0] = 0.f; sf[nt][1] = 0.f; sf[nt][2] = 0.f; sf[nt][3] = 0.f;
            #pragma unroll
            for (int kc = 0; kc < 8; ++kc) {
                uint2 bb = *reinterpret_cast<const uint2*>(
                    &Ks[(nt * 8 + g) * KPITCH + kc * 8 + 2 * tig]);
                mma_tf32(sf[nt], qf[kc], bb.x, bb.y);
            }
        }

        // ---- online softmax (rows wr+g and wr+g+8; quad reduction) ----
        float mtA = sf[0][0], mtB = sf[0][2];
        #pragma unroll
        for (int nt = 0; nt < 8; ++nt) {
            mtA = fmaxf(mtA, fmaxf(sf[nt][0], sf[nt][1]));
            mtB = fmaxf(mtB, fmaxf(sf[nt][2], sf[nt][3]));
        }
        mtA = fmaxf(mtA, __shfl_xor_sync(0xffffffffu, mtA, 1));
        mtA = fmaxf(mtA, __shfl_xor_sync(0xffffffffu, mtA, 2));
        mtB = fmaxf(mtB, __shfl_xor_sync(0xffffffffu, mtB, 1));
        mtB = fmaxf(mtB, __shfl_xor_sync(0xffffffffu, mtB, 2));

        const float mnA = fmaxf(mA, mtA);
        const float mnB = fmaxf(mB, mtB);
        const float cA = fast_ex2(mA - mnA);
        const float cB = fast_ex2(mB - mnB);

        float sumA = 0.f, sumB = 0.f;
        #pragma unroll
        for (int nt = 0; nt < 8; ++nt) {
            sf[nt][0] = fast_ex2(sf[nt][0] - mnA);
            sf[nt][1] = fast_ex2(sf[nt][1] - mnA);
            sf[nt][2] = fast_ex2(sf[nt][2] - mnB);
            sf[nt][3] = fast_ex2(sf[nt][3] - mnB);
            sumA += sf[nt][0] + sf[nt][1];
            sumB += sf[nt][2] + sf[nt][3];
        }
        sumA += __shfl_xor_sync(0xffffffffu, sumA, 1);
        sumA += __shfl_xor_sync(0xffffffffu, sumA, 2);
        sumB += __shfl_xor_sync(0xffffffffu, sumB, 1);
        sumB += __shfl_xor_sync(0xffffffffu, sumB, 2);

        lA = lA * cA + sumA; mA = mnA;
        lB = lB * cB + sumB; mB = mnB;
        #pragma unroll
        for (int nt = 0; nt < 8; ++nt) {
            of[nt][0] *= cA; of[nt][1] *= cA;
            of[nt][2] *= cB; of[nt][3] *= cB;
        }

        // ---- P (tf32) -> PQ rows wr..wr+15 (warp-local) ----
        #pragma unroll
        for (int nt = 0; nt < 8; ++nt) {
            uint2 p0, p1;
            p0.x = f2tf32(sf[nt][0]); p0.y = f2tf32(sf[nt][1]);
            p1.x = f2tf32(sf[nt][2]); p1.y = f2tf32(sf[nt][3]);
            *reinterpret_cast<uint2*>(&PQ[(wr + g)     * PPITCH + nt * 8 + 2 * tig]) = p0;
            *reinterpret_cast<uint2*>(&PQ[(wr + g + 8) * PPITCH + nt * 8 + 2 * tig]) = p1;
        }
        __syncwarp();

        // ---- O += P V (A frags from PQ, B frags LDS.64 from Vt) ----
        uint32_t pf[8][4];
        #pragma unroll
        for (int kc = 0; kc < 8; ++kc) {
            pf[kc][0] = PQ[(wr + g)     * PPITCH + kc * 8 + tig];
            pf[kc][1] = PQ[(wr + g + 8) * PPITCH + kc * 8 + tig];
            pf[kc][2] = PQ[(wr + g)     * PPITCH + kc * 8 + tig + 4];
            pf[kc][3] = PQ[(wr + g + 8) * PPITCH + kc * 8 + tig + 4];
        }
        #pragma unroll
        for (int nt = 0; nt < 8; ++nt) {
            #pragma unroll
            for (int kc = 0; kc < 8; ++kc) {
                uint2 bb = *reinterpret_cast<const uint2*>(
                    &Vt[(nt * 8 + g) * KPITCH + kc * 8 + 2 * tig]);
                mma_tf32(of[nt], pf[kc], bb.x, bb.y);
            }
        }
    }

    // ---- epilogue: g_Ct[b*S + q, h*64 + d] ----
    {
        const float invA = 1.f / lA;
        const float invB = 1.f / lB;
        const int b = bh >> 4, h = bh & 15;
        const size_t rowA = (size_t)b * SS + q0 + wr + g;
        const size_t rowB = rowA + 8;
        #pragma unroll
        for (int nt = 0; nt < 8; ++nt) {
            const int col = h * 64 + nt * 8 + 2 * tig;
            *reinterpret_cast<float2*>(&g_Ct[rowA * DD + col]) =
                make_float2(of[nt][0] * invA, of[nt][1] * invA);
            *reinterpret_cast<float2*>(&g_Ct[rowB * DD + col]) =
                make_float2(of[nt][2] * invB, of[nt][3] * invB);
        }
    }
}

extern "C" void kernel_launch(void* const* d_in, const int* in_sizes, int n_in,
                              void* d_out, int out_size)
{
    const float* x  = (const float*)d_in[0];
    const float* Wq = (const float*)d_in[1];
    const float* Wk = (const float*)d_in[2];
    const float* Wv = (const float*)d_in[3];
    const float* Wo = (const float*)d_in[4];
    float* out = (float*)d_out;

    (void)in_sizes; (void)n_in; (void)out_size;

    cudaFuncSetAttribute(flash_attn_t, cudaFuncAttributeMaxDynamicSharedMemorySize, FA_SMEM);

    qkv_gemm_t<<<dim3(M_TOT / 128, HH, 3), 256>>>(x, Wq, Wk, Wv);
    flash_attn_t<<<dim3(SS / 128, BB * HH), 256, FA_SMEM>>>();
    out_gemm_t<<<dim3(M_TOT / 128, DD / 64), 256>>>(Wo, out);
}

// round 5
// speedup vs baseline: 1.4510x; 1.4510x over previous
#include <cuda_runtime.h>
#include <cstdint>

#define BB 4
#define SS 2048
#define DD 1024
#define HH 16
#define DK 64
#define M_TOT (BB*SS)   // 8192

__device__ float g_Q[BB*HH*SS*DK];
__device__ float g_K[BB*HH*SS*DK];
__device__ float g_V[BB*HH*SS*DK];
__device__ float g_Ct[(size_t)M_TOT*DD];

// ---------------------------------------------------------------------------
// helpers
// ---------------------------------------------------------------------------
__device__ __forceinline__ uint32_t f2tf32(float f) {
    uint32_t r;
    asm("cvt.rna.tf32.f32 %0, %1;" : "=r"(r) : "f"(f));
    return r;
}

__device__ __forceinline__ float fast_ex2(float x) {
    float y;
    asm("ex2.approx.ftz.f32 %0, %1;" : "=f"(y) : "f"(x));
    return y;
}

__device__ __forceinline__ void mma_tf32(float* c, const uint32_t* a, uint32_t b0, uint32_t b1) {
    asm volatile(
        "mma.sync.aligned.m16n8k8.row.col.f32.tf32.tf32.f32 "
        "{%0,%1,%2,%3}, {%4,%5,%6,%7}, {%8,%9}, {%0,%1,%2,%3};"
        : "+f"(c[0]), "+f"(c[1]), "+f"(c[2]), "+f"(c[3])
        : "r"(a[0]), "r"(a[1]), "r"(a[2]), "r"(a[3]), "r"(b0), "r"(b1));
}

__device__ __forceinline__ void ldsm4(uint32_t* r, uint32_t addr) {
    asm volatile("ldmatrix.sync.aligned.m8n8.x4.shared.b16 {%0,%1,%2,%3}, [%4];"
        : "=r"(r[0]), "=r"(r[1]), "=r"(r[2]), "=r"(r[3]) : "r"(addr));
}

__device__ __forceinline__ uint32_t smem_u32(const void* p) {
    uint32_t a;
    asm("{ .reg .u64 t; cvta.to.shared.u64 t, %1; cvt.u32.u64 %0, t; }" : "=r"(a) : "l"(p));
    return a;
}

// Per-lane LDSM address offsets:
//   A-style (16x8 tf32 tile):  tiles = (rows 0-7 / 8-15) x (cols 0-3 / 4-7)
//     row_off = ((l>>3)&1)*8 + (l&7), col_off = ((l>>4)&1)*4
//   B-style (two 8-n tiles):   tiles = (nt pair) x (k 0-3 / 4-7)
//     row_off = ((l>>4)&1)*8 + (l&7), col_off = ((l>>3)&1)*4

// ---------------------------------------------------------------------------
// QKV projection GEMM: 128x64 tile, BK=16, 256 threads, warp tile 32x32.
// A: As[m][k] pitch 20.  B: Bt[n][k] pitch 20 (transposed at staging).
// ---------------------------------------------------------------------------
#define GAP 20

__global__ __launch_bounds__(256) void qkv_gemm_t(
    const float* __restrict__ x,
    const float* __restrict__ Wq,
    const float* __restrict__ Wk,
    const float* __restrict__ Wv)
{
    __shared__ uint32_t As[128 * GAP];
    __shared__ uint32_t Bt[64 * GAP];

    const int m0 = blockIdx.x * 128;
    const int h  = blockIdx.y;
    const int z  = blockIdx.z;
    const float* W = (z == 0) ? Wq : (z == 1) ? Wk : Wv;
    float* Cout    = (z == 0) ? g_Q : (z == 1) ? g_K : g_V;
    const float* Wh = W + (size_t)h * DD * DK;

    const int tid  = threadIdx.x;
    const int warp = tid >> 5;
    const int lane = tid & 31;
    const int g    = lane >> 2;
    const int tig  = lane & 3;
    const int wm   = (warp & 3) * 32;
    const int wn   = (warp >> 2) * 32;

    const uint32_t as_b = smem_u32(As);
    const uint32_t bt_b = smem_u32(Bt);
    const int rA = ((lane >> 3) & 1) * 8 + (lane & 7);   // A-style row off
    const int cA = ((lane >> 4) & 1) * 4;                // A-style col off
    const int rB = ((lane >> 4) & 1) * 8 + (lane & 7);   // B-style row off
    const int cB = ((lane >> 3) & 1) * 4;                // B-style col off

    // A loader: row=tid>>1 (0..127), 8 k at (tid&1)*8
    const int ar = tid >> 1;
    const int ac = (tid & 1) * 8;
    // B loader: k = tid&15, n0 = (tid>>4)*4
    const int bk = tid & 15;
    const int bn = (tid >> 4) * 4;

    float acc[2][4][4];
    #pragma unroll
    for (int i = 0; i < 2; ++i)
        #pragma unroll
        for (int j = 0; j < 4; ++j)
            #pragma unroll
            for (int l2 = 0; l2 < 4; ++l2) acc[i][j][l2] = 0.f;

    float4 av0, av1, bv;
    av0 = *reinterpret_cast<const float4*>(&x[(size_t)(m0 + ar) * DD + ac]);
    av1 = *reinterpret_cast<const float4*>(&x[(size_t)(m0 + ar) * DD + ac + 4]);
    bv  = *reinterpret_cast<const float4*>(&Wh[(size_t)bk * DK + bn]);

    for (int k0 = 0; k0 < DD; k0 += 16) {
        {
            uint4 t0, t1;
            t0.x = f2tf32(av0.x); t0.y = f2tf32(av0.y); t0.z = f2tf32(av0.z); t0.w = f2tf32(av0.w);
            t1.x = f2tf32(av1.x); t1.y = f2tf32(av1.y); t1.z = f2tf32(av1.z); t1.w = f2tf32(av1.w);
            *reinterpret_cast<uint4*>(&As[ar * GAP + ac])     = t0;
            *reinterpret_cast<uint4*>(&As[ar * GAP + ac + 4]) = t1;
            Bt[(bn + 0) * GAP + bk] = f2tf32(bv.x);
            Bt[(bn + 1) * GAP + bk] = f2tf32(bv.y);
            Bt[(bn + 2) * GAP + bk] = f2tf32(bv.z);
            Bt[(bn + 3) * GAP + bk] = f2tf32(bv.w);
        }
        __syncthreads();

        if (k0 + 16 < DD) {
            av0 = *reinterpret_cast<const float4*>(&x[(size_t)(m0 + ar) * DD + k0 + 16 + ac]);
            av1 = *reinterpret_cast<const float4*>(&x[(size_t)(m0 + ar) * DD + k0 + 16 + ac + 4]);
            bv  = *reinterpret_cast<const float4*>(&Wh[(size_t)(k0 + 16 + bk) * DK + bn]);
        }

        #pragma unroll
        for (int kc = 0; kc < 2; ++kc) {
            uint32_t af[2][4];
            #pragma unroll
            for (int mt = 0; mt < 2; ++mt)
                ldsm4(af[mt], as_b + ((wm + mt * 16 + rA) * GAP + kc * 8 + cA) * 4);
            #pragma unroll
            for (int ntp = 0; ntp < 2; ++ntp) {
                uint32_t bf[4];
                ldsm4(bf, bt_b + ((wn + ntp * 16 + rB) * GAP + kc * 8 + cB) * 4);
                #pragma unroll
                for (int mt = 0; mt < 2; ++mt) {
                    mma_tf32(acc[mt][ntp * 2 + 0], af[mt], bf[0], bf[1]);
                    mma_tf32(acc[mt][ntp * 2 + 1], af[mt], bf[2], bf[3]);
                }
            }
        }
        __syncthreads();
    }

    // Epilogue: [B,H,S,64]
    #pragma unroll
    for (int mt = 0; mt < 2; ++mt) {
        #pragma unroll
        for (int nt = 0; nt < 4; ++nt) {
            const int col = wn + nt * 8 + 2 * tig;
            #pragma unroll
            for (int rh = 0; rh < 2; ++rh) {
                const int m = m0 + wm + mt * 16 + g + rh * 8;
                const int b = m >> 11;
                const int s = m & 2047;
                float2 v = make_float2(acc[mt][nt][rh * 2], acc[mt][nt][rh * 2 + 1]);
                *reinterpret_cast<float2*>(
                    &Cout[(((size_t)(b * HH + h)) * SS + s) * DK + col]) = v;
            }
        }
    }
}

// ---------------------------------------------------------------------------
// Output projection GEMM: same structure, B tile from Wo (1024-wide rows).
// ---------------------------------------------------------------------------
__global__ __launch_bounds__(256) void out_gemm_t(
    const float* __restrict__ Wo, float* __restrict__ out)
{
    __shared__ uint32_t As[128 * GAP];
    __shared__ uint32_t Bt[64 * GAP];

    const int m0 = blockIdx.x * 128;
    const int n0 = blockIdx.y * 64;

    const int tid  = threadIdx.x;
    const int warp = tid >> 5;
    const int lane = tid & 31;
    const int g    = lane >> 2;
    const int tig  = lane & 3;
    const int wm   = (warp & 3) * 32;
    const int wn   = (warp >> 2) * 32;

    const uint32_t as_b = smem_u32(As);
    const uint32_t bt_b = smem_u32(Bt);
    const int rA = ((lane >> 3) & 1) * 8 + (lane & 7);
    const int cA = ((lane >> 4) & 1) * 4;
    const int rB = ((lane >> 4) & 1) * 8 + (lane & 7);
    const int cB = ((lane >> 3) & 1) * 4;

    const int ar = tid >> 1;
    const int ac = (tid & 1) * 8;
    const int bk = tid & 15;
    const int bn = (tid >> 4) * 4;

    float acc[2][4][4];
    #pragma unroll
    for (int i = 0; i < 2; ++i)
        #pragma unroll
        for (int j = 0; j < 4; ++j)
            #pragma unroll
            for (int l2 = 0; l2 < 4; ++l2) acc[i][j][l2] = 0.f;

    float4 av0, av1, bv;
    av0 = *reinterpret_cast<const float4*>(&g_Ct[(size_t)(m0 + ar) * DD + ac]);
    av1 = *reinterpret_cast<const float4*>(&g_Ct[(size_t)(m0 + ar) * DD + ac + 4]);
    bv  = *reinterpret_cast<const float4*>(&Wo[(size_t)bk * DD + n0 + bn]);

    for (int k0 = 0; k0 < DD; k0 += 16) {
        {
            uint4 t0, t1;
            t0.x = f2tf32(av0.x); t0.y = f2tf32(av0.y); t0.z = f2tf32(av0.z); t0.w = f2tf32(av0.w);
            t1.x = f2tf32(av1.x); t1.y = f2tf32(av1.y); t1.z = f2tf32(av1.z); t1.w = f2tf32(av1.w);
            *reinterpret_cast<uint4*>(&As[ar * GAP + ac])     = t0;
            *reinterpret_cast<uint4*>(&As[ar * GAP + ac + 4]) = t1;
            Bt[(bn + 0) * GAP + bk] = f2tf32(bv.x);
            Bt[(bn + 1) * GAP + bk] = f2tf32(bv.y);
            Bt[(bn + 2) * GAP + bk] = f2tf32(bv.z);
            Bt[(bn + 3) * GAP + bk] = f2tf32(bv.w);
        }
        __syncthreads();

        if (k0 + 16 < DD) {
            av0 = *reinterpret_cast<const float4*>(&g_Ct[(size_t)(m0 + ar) * DD + k0 + 16 + ac]);
            av1 = *reinterpret_cast<const float4*>(&g_Ct[(size_t)(m0 + ar) * DD + k0 + 16 + ac + 4]);
            bv  = *reinterpret_cast<const float4*>(&Wo[(size_t)(k0 + 16 + bk) * DD + n0 + bn]);
        }

        #pragma unroll
        for (int kc = 0; kc < 2; ++kc) {
            uint32_t af[2][4];
            #pragma unroll
            for (int mt = 0; mt < 2; ++mt)
                ldsm4(af[mt], as_b + ((wm + mt * 16 + rA) * GAP + kc * 8 + cA) * 4);
            #pragma unroll
            for (int ntp = 0; ntp < 2; ++ntp) {
                uint32_t bf[4];
                ldsm4(bf, bt_b + ((wn + ntp * 16 + rB) * GAP + kc * 8 + cB) * 4);
                #pragma unroll
                for (int mt = 0; mt < 2; ++mt) {
                    mma_tf32(acc[mt][ntp * 2 + 0], af[mt], bf[0], bf[1]);
                    mma_tf32(acc[mt][ntp * 2 + 1], af[mt], bf[2], bf[3]);
                }
            }
        }
        __syncthreads();
    }

    #pragma unroll
    for (int mt = 0; mt < 2; ++mt) {
        #pragma unroll
        for (int nt = 0; nt < 4; ++nt) {
            const int col = n0 + wn + nt * 8 + 2 * tig;
            #pragma unroll
            for (int rh = 0; rh < 2; ++rh) {
                const int m = m0 + wm + mt * 16 + g + rh * 8;
                float2 v = make_float2(acc[mt][nt][rh * 2], acc[mt][nt][rh * 2 + 1]);
                *reinterpret_cast<float2*>(&out[(size_t)m * DD + col]) = v;
            }
        }
    }
}

// ---------------------------------------------------------------------------
// Flash attention, LDSM edition.
//   CTA = 128 q-rows of one (b,h); 256 threads / 8 warps; warp = 16 q rows.
//   QP[q=128][68]: Q staging, then P (warp-local rows).
//   Ks[s=64][68]:  K natural layout = B operand of Q K^T (n = s rows).
//   Vt[d=64][68]:  V transposed = B operand of P V (n = d rows).
// ---------------------------------------------------------------------------
#define FPITCH 68
#define QP_OFF 0
#define KS_OFF 34816
#define VT_OFF 52224
#define FA_SMEM 69632

__global__ __launch_bounds__(256, 2) void flash_attn_t()
{
    extern __shared__ char smem[];
    uint32_t* QP = reinterpret_cast<uint32_t*>(smem + QP_OFF);
    uint32_t* Ks = reinterpret_cast<uint32_t*>(smem + KS_OFF);
    uint32_t* Vt = reinterpret_cast<uint32_t*>(smem + VT_OFF);

    const int tid  = threadIdx.x;
    const int w    = tid >> 5;
    const int lane = tid & 31;
    const int g    = lane >> 2;
    const int tig  = lane & 3;
    const int wr   = w * 16;

    const uint32_t qp_b = smem_u32(QP);
    const uint32_t ks_b = smem_u32(Ks);
    const uint32_t vt_b = smem_u32(Vt);
    const int rA = ((lane >> 3) & 1) * 8 + (lane & 7);
    const int cA = ((lane >> 4) & 1) * 4;
    const int rB = ((lane >> 4) & 1) * 8 + (lane & 7);
    const int cB = ((lane >> 3) & 1) * 4;

    const int q0 = blockIdx.x * 128;
    const int bh = blockIdx.y;
    const float* Qp = g_Q + (size_t)bh * SS * DK;
    const float* Kp = g_K + (size_t)bh * SS * DK;
    const float* Vp = g_V + (size_t)bh * SS * DK;

    // ---- stage Q (scaled by 0.125*log2e) ----
    {
        const float QSC = 0.125f * 1.4426950408889634f;
        const int row = tid >> 1;
        const int dh  = (tid & 1) * 32;
        const float4* src = reinterpret_cast<const float4*>(Qp + (size_t)(q0 + row) * DK + dh);
        #pragma unroll
        for (int j = 0; j < 8; ++j) {
            float4 v = src[j];
            uint4 t;
            t.x = f2tf32(v.x * QSC); t.y = f2tf32(v.y * QSC);
            t.z = f2tf32(v.z * QSC); t.w = f2tf32(v.w * QSC);
            *reinterpret_cast<uint4*>(&QP[row * FPITCH + dh + 4 * j]) = t;
        }
    }
    __syncthreads();

    uint32_t qf[8][4];
    #pragma unroll
    for (int kc = 0; kc < 8; ++kc)
        ldsm4(qf[kc], qp_b + ((wr + rA) * FPITCH + kc * 8 + cA) * 4);

    float of[8][4];
    #pragma unroll
    for (int nt = 0; nt < 8; ++nt)
        #pragma unroll
        for (int i = 0; i < 4; ++i) of[nt][i] = 0.f;
    float mA = -1e30f, mB = -1e30f, lA = 0.f, lB = 0.f;

    // loader mappings
    const int ls  = tid & 63;          // s row (K and V)
    const int kdq = (tid >> 6) * 16;   // K d-chunk base
    const int vdb = (tid >> 6) * 4;    // V d base

    for (int kt = 0; kt < SS; kt += 64) {
        __syncthreads();   // prev tile fully consumed

        // ---- stage K [s][d] (vector) and V^T [d][s] (scalar, conflict-free) ----
        {
            const float4* ksrc = reinterpret_cast<const float4*>(Kp + (size_t)(kt + ls) * DK + kdq);
            #pragma unroll
            for (int j = 0; j < 4; ++j) {
                float4 kv = ksrc[j];
                uint4 t;
                t.x = f2tf32(kv.x); t.y = f2tf32(kv.y);
                t.z = f2tf32(kv.z); t.w = f2tf32(kv.w);
                *reinterpret_cast<uint4*>(&Ks[ls * FPITCH + kdq + 4 * j]) = t;
            }
            #pragma unroll
            for (int c = 0; c < 4; ++c) {
                const int d0 = vdb + 16 * c;
                float4 vv = *reinterpret_cast<const float4*>(Vp + (size_t)(kt + ls) * DK + d0);
                Vt[(d0 + 0) * FPITCH + ls] = f2tf32(vv.x);
                Vt[(d0 + 1) * FPITCH + ls] = f2tf32(vv.y);
                Vt[(d0 + 2) * FPITCH + ls] = f2tf32(vv.z);
                Vt[(d0 + 3) * FPITCH + ls] = f2tf32(vv.w);
            }
        }
        __syncthreads();

        // ---- S = Q K^T ----
        float sf[8][4];
        #pragma unroll
        for (int ntp = 0; ntp < 4; ++ntp) {
            #pragma unroll
            for (int i = 0; i < 4; ++i) { sf[2 * ntp][i] = 0.f; sf[2 * ntp + 1][i] = 0.f; }
            #pragma unroll
            for (int kc = 0; kc < 8; ++kc) {
                uint32_t bf[4];
                ldsm4(bf, ks_b + ((ntp * 16 + rB) * FPITCH + kc * 8 + cB) * 4);
                mma_tf32(sf[2 * ntp + 0], qf[kc], bf[0], bf[1]);
                mma_tf32(sf[2 * ntp + 1], qf[kc], bf[2], bf[3]);
            }
        }

        // ---- online softmax (rows wr+g, wr+g+8) ----
        float mtA = sf[0][0], mtB = sf[0][2];
        #pragma unroll
        for (int nt = 0; nt < 8; ++nt) {
            mtA = fmaxf(mtA, fmaxf(sf[nt][0], sf[nt][1]));
            mtB = fmaxf(mtB, fmaxf(sf[nt][2], sf[nt][3]));
        }
        mtA = fmaxf(mtA, __shfl_xor_sync(0xffffffffu, mtA, 1));
        mtA = fmaxf(mtA, __shfl_xor_sync(0xffffffffu, mtA, 2));
        mtB = fmaxf(mtB, __shfl_xor_sync(0xffffffffu, mtB, 1));
        mtB = fmaxf(mtB, __shfl_xor_sync(0xffffffffu, mtB, 2));

        const float mnA = fmaxf(mA, mtA);
        const float mnB = fmaxf(mB, mtB);
        const float corA = fast_ex2(mA - mnA);
        const float corB = fast_ex2(mB - mnB);

        float sumA = 0.f, sumB = 0.f;
        #pragma unroll
        for (int nt = 0; nt < 8; ++nt) {
            sf[nt][0] = fast_ex2(sf[nt][0] - mnA);
            sf[nt][1] = fast_ex2(sf[nt][1] - mnA);
            sf[nt][2] = fast_ex2(sf[nt][2] - mnB);
            sf[nt][3] = fast_ex2(sf[nt][3] - mnB);
            sumA += sf[nt][0] + sf[nt][1];
            sumB += sf[nt][2] + sf[nt][3];
        }
        sumA += __shfl_xor_sync(0xffffffffu, sumA, 1);
        sumA += __shfl_xor_sync(0xffffffffu, sumA, 2);
        sumB += __shfl_xor_sync(0xffffffffu, sumB, 1);
        sumB += __shfl_xor_sync(0xffffffffu, sumB, 2);

        lA = lA * corA + sumA; mA = mnA;
        lB = lB * corB + sumB; mB = mnB;
        #pragma unroll
        for (int nt = 0; nt < 8; ++nt) {
            of[nt][0] *= corA; of[nt][1] *= corA;
            of[nt][2] *= corB; of[nt][3] *= corB;
        }

        // ---- P -> QP rows wr..wr+15 (warp-local) ----
        #pragma unroll
        for (int nt = 0; nt < 8; ++nt) {
            uint2 p0, p1;
            p0.x = f2tf32(sf[nt][0]); p0.y = f2tf32(sf[nt][1]);
            p1.x = f2tf32(sf[nt][2]); p1.y = f2tf32(sf[nt][3]);
            *reinterpret_cast<uint2*>(&QP[(wr + g)     * FPITCH + nt * 8 + 2 * tig]) = p0;
            *reinterpret_cast<uint2*>(&QP[(wr + g + 8) * FPITCH + nt * 8 + 2 * tig]) = p1;
        }
        __syncwarp();

        // ---- O += P V ----
        uint32_t pf[8][4];
        #pragma unroll
        for (int kc = 0; kc < 8; ++kc)
            ldsm4(pf[kc], qp_b + ((wr + rA) * FPITCH + kc * 8 + cA) * 4);
        #pragma unroll
        for (int ntp = 0; ntp < 4; ++ntp) {
            #pragma unroll
            for (int kc = 0; kc < 8; ++kc) {
                uint32_t bf[4];
                ldsm4(bf, vt_b + ((ntp * 16 + rB) * FPITCH + kc * 8 + cB) * 4);
                mma_tf32(of[2 * ntp + 0], pf[kc], bf[0], bf[1]);
                mma_tf32(of[2 * ntp + 1], pf[kc], bf[2], bf[3]);
            }
        }
    }

    // ---- epilogue ----
    {
        const float invA = 1.f / lA;
        const float invB = 1.f / lB;
        const int b = bh >> 4, h = bh & 15;
        const size_t rowA = (size_t)b * SS + q0 + wr + g;
        const size_t rowB = rowA + 8;
        #pragma unroll
        for (int nt = 0; nt < 8; ++nt) {
            const int col = h * 64 + nt * 8 + 2 * tig;
            *reinterpret_cast<float2*>(&g_Ct[rowA * DD + col]) =
                make_float2(of[nt][0] * invA, of[nt][1] * invA);
            *reinterpret_cast<float2*>(&g_Ct[rowB * DD + col]) =
                make_float2(of[nt][2] * invB, of[nt][3] * invB);
        }
    }
}

extern "C" void kernel_launch(void* const* d_in, const int* in_sizes, int n_in,
                              void* d_out, int out_size)
{
    const float* x  = (const float*)d_in[0];
    const float* Wq = (const float*)d_in[1];
    const float* Wk = (const float*)d_in[2];
    const float* Wv = (const float*)d_in[3];
    const float* Wo = (const float*)d_in[4];
    float* out = (float*)d_out;

    (void)in_sizes; (void)n_in; (void)out_size;

    cudaFuncSetAttribute(flash_attn_t, cudaFuncAttributeMaxDynamicSharedMemorySize, FA_SMEM);

    qkv_gemm_t<<<dim3(M_TOT / 128, HH, 3), 256>>>(x, Wq, Wk, Wv);
    flash_attn_t<<<dim3(SS / 128, BB * HH), 256, FA_SMEM>>>();
    out_gemm_t<<<dim3(M_TOT / 128, DD / 64), 256>>>(Wo, out);
}

// round 6
// speedup vs baseline: 2.5136x; 1.7323x over previous
#include <cuda_runtime.h>
#include <cuda_fp16.h>
#include <cstdint>

#define BB 4
#define SS 2048
#define DD 1024
#define HH 16
#define DK 64
#define M_TOT (BB*SS)   // 8192

// Scratch (allocation-free rule: __device__ globals) — fp16 intermediates
__device__ __half g_Q[BB*HH*SS*DK];
__device__ __half g_K[BB*HH*SS*DK];
__device__ __half g_V[BB*HH*SS*DK];
__device__ __half g_Ct[(size_t)M_TOT*DD];

// ---------------------------------------------------------------------------
// helpers
// ---------------------------------------------------------------------------
__device__ __forceinline__ float fast_ex2(float x) {
    float y;
    asm("ex2.approx.ftz.f32 %0, %1;" : "=f"(y) : "f"(x));
    return y;
}

__device__ __forceinline__ void mma_f16(float* c, const uint32_t* a, uint32_t b0, uint32_t b1) {
    asm volatile(
        "mma.sync.aligned.m16n8k16.row.col.f32.f16.f16.f32 "
        "{%0,%1,%2,%3}, {%4,%5,%6,%7}, {%8,%9}, {%0,%1,%2,%3};"
        : "+f"(c[0]), "+f"(c[1]), "+f"(c[2]), "+f"(c[3])
        : "r"(a[0]), "r"(a[1]), "r"(a[2]), "r"(a[3]), "r"(b0), "r"(b1));
}

__device__ __forceinline__ void ldsm4(uint32_t* r, uint32_t addr) {
    asm volatile("ldmatrix.sync.aligned.m8n8.x4.shared.b16 {%0,%1,%2,%3}, [%4];"
        : "=r"(r[0]), "=r"(r[1]), "=r"(r[2]), "=r"(r[3]) : "r"(addr));
}
__device__ __forceinline__ void ldsm4t(uint32_t* r, uint32_t addr) {
    asm volatile("ldmatrix.sync.aligned.m8n8.x4.trans.shared.b16 {%0,%1,%2,%3}, [%4];"
        : "=r"(r[0]), "=r"(r[1]), "=r"(r[2]), "=r"(r[3]) : "r"(addr));
}

__device__ __forceinline__ uint32_t smem_u32(const void* p) {
    uint32_t a;
    asm("{ .reg .u64 t; cvta.to.shared.u64 t, %1; cvt.u32.u64 %0, t; }" : "=r"(a) : "l"(p));
    return a;
}

__device__ __forceinline__ uint32_t h2pack(float a, float b) {
    __half2 h = __floats2half2_rn(a, b);
    return *reinterpret_cast<uint32_t*>(&h);
}

// Lane offsets (b16 8x8 tiles):
//  A-style (non-trans, [m][k] rows):  a0(m0-7,k0-7) a1(m8-15,k0-7) a2(m0-7,k8-15) a3(m8-15,k8-15)
//    rA = (l&7) + ((l>>3)&1)*8 ; cA = ((l>>4)&1)*8     (halfs)
//  Bn-style (non-trans, [n][k] rows): t0(n0-7,k0-7) t1(n0-7,k8-15) t2(n8-15,k0-7) t3(n8-15,k8-15)
//    rBn = ((l>>4)&1)*8 + (l&7) ; cBn = ((l>>3)&1)*8   -> frags {r0,r1},{r2,r3}
//  Bt-style (trans, [k][n] rows):     t0(k0-7,n0-7) t1(k8-15,n0-7) t2(k0-7,n8-15) t3(k8-15,n8-15)
//    rBt = (l&7) + ((l>>3)&1)*8 ; cBt = ((l>>4)&1)*8   -> frags {r0,r1},{r2,r3}

#define QSC_F (0.125f * 1.4426950408889634f)

// ---------------------------------------------------------------------------
// QKV projection GEMM: block 128x64, BK=32, 256 thr, 8 warps (4m x 2n), warp 32x32.
// As[m][40] halfs, Bs[k][72] halfs (k-major, ldsm.trans for B frags).
// Q output is pre-scaled by 0.125*log2(e).
// ---------------------------------------------------------------------------
#define APH 40
#define BPH 72

__global__ __launch_bounds__(256, 2) void qkv_gemm_t(
    const float* __restrict__ x,
    const float* __restrict__ Wq,
    const float* __restrict__ Wk,
    const float* __restrict__ Wv)
{
    __shared__ __align__(16) __half As[128 * APH];
    __shared__ __align__(16) __half Bs[32 * BPH];

    const int m0 = blockIdx.x * 128;
    const int h  = blockIdx.y;
    const int z  = blockIdx.z;
    const float* W = (z == 0) ? Wq : (z == 1) ? Wk : Wv;
    __half* Cout   = (z == 0) ? g_Q : (z == 1) ? g_K : g_V;
    const float outsc = (z == 0) ? QSC_F : 1.0f;
    const float* Wh = W + (size_t)h * DD * DK;

    const int tid  = threadIdx.x;
    const int warp = tid >> 5;
    const int lane = tid & 31;
    const int g    = lane >> 2;
    const int tig  = lane & 3;
    const int wm   = (warp & 3) * 32;
    const int wn   = (warp >> 2) * 32;

    const uint32_t as_b = smem_u32(As);
    const uint32_t bs_b = smem_u32(Bs);
    const int rA  = (lane & 7) + ((lane >> 3) & 1) * 8;
    const int cA  = ((lane >> 4) & 1) * 8;
    const int rBt = (lane & 7) + ((lane >> 3) & 1) * 8;
    const int cBt = ((lane >> 4) & 1) * 8;

    // A loader: m = tid&127, kh = (tid>>7)*16 (16 floats -> 16 halfs)
    const int am = tid & 127;
    const int akh = (tid >> 7) * 16;
    // B loader: k = tid>>3 (0..31), n8 = (tid&7)*8
    const int bkr = tid >> 3;
    const int bn8 = (tid & 7) * 8;

    float acc[2][4][4];
    #pragma unroll
    for (int i = 0; i < 2; ++i)
        #pragma unroll
        for (int j = 0; j < 4; ++j)
            #pragma unroll
            for (int l2 = 0; l2 < 4; ++l2) acc[i][j][l2] = 0.f;

    float4 av[4], bv[2];
    #pragma unroll
    for (int j = 0; j < 4; ++j)
        av[j] = *reinterpret_cast<const float4*>(&x[(size_t)(m0 + am) * DD + akh + 4 * j]);
    #pragma unroll
    for (int j = 0; j < 2; ++j)
        bv[j] = *reinterpret_cast<const float4*>(&Wh[(size_t)bkr * DK + bn8 + 4 * j]);

    for (int k0 = 0; k0 < DD; k0 += 32) {
        {
            uint32_t aw[8];
            #pragma unroll
            for (int j = 0; j < 4; ++j) {
                aw[2 * j]     = h2pack(av[j].x, av[j].y);
                aw[2 * j + 1] = h2pack(av[j].z, av[j].w);
            }
            *reinterpret_cast<uint4*>(&As[am * APH + akh])     = *reinterpret_cast<uint4*>(&aw[0]);
            *reinterpret_cast<uint4*>(&As[am * APH + akh + 8]) = *reinterpret_cast<uint4*>(&aw[4]);
            uint32_t bw[4];
            bw[0] = h2pack(bv[0].x, bv[0].y);
            bw[1] = h2pack(bv[0].z, bv[0].w);
            bw[2] = h2pack(bv[1].x, bv[1].y);
            bw[3] = h2pack(bv[1].z, bv[1].w);
            *reinterpret_cast<uint4*>(&Bs[bkr * BPH + bn8]) = *reinterpret_cast<uint4*>(bw);
        }
        __syncthreads();

        if (k0 + 32 < DD) {
            #pragma unroll
            for (int j = 0; j < 4; ++j)
                av[j] = *reinterpret_cast<const float4*>(&x[(size_t)(m0 + am) * DD + k0 + 32 + akh + 4 * j]);
            #pragma unroll
            for (int j = 0; j < 2; ++j)
                bv[j] = *reinterpret_cast<const float4*>(&Wh[(size_t)(k0 + 32 + bkr) * DK + bn8 + 4 * j]);
        }

        #pragma unroll
        for (int kc = 0; kc < 2; ++kc) {
            uint32_t af[2][4];
            #pragma unroll
            for (int mt = 0; mt < 2; ++mt)
                ldsm4(af[mt], as_b + ((wm + mt * 16 + rA) * APH + kc * 16 + cA) * 2);
            uint32_t bf[4];
            ldsm4t(bf, bs_b + ((kc * 16 + rBt) * BPH + wn + cBt) * 2);
            uint32_t bf2[4];
            ldsm4t(bf2, bs_b + ((kc * 16 + rBt) * BPH + wn + 16 + cBt) * 2);
            #pragma unroll
            for (int mt = 0; mt < 2; ++mt) {
                mma_f16(acc[mt][0], af[mt], bf[0],  bf[1]);
                mma_f16(acc[mt][1], af[mt], bf[2],  bf[3]);
                mma_f16(acc[mt][2], af[mt], bf2[0], bf2[1]);
                mma_f16(acc[mt][3], af[mt], bf2[2], bf2[3]);
            }
        }
        __syncthreads();
    }

    // Epilogue: write [B,H,S,64] halfs (Q pre-scaled)
    #pragma unroll
    for (int mt = 0; mt < 2; ++mt) {
        #pragma unroll
        for (int nt = 0; nt < 4; ++nt) {
            const int col = wn + nt * 8 + 2 * tig;
            #pragma unroll
            for (int rh = 0; rh < 2; ++rh) {
                const int m = m0 + wm + mt * 16 + g + rh * 8;
                const int b = m >> 11;
                const int s = m & 2047;
                uint32_t v = h2pack(acc[mt][nt][rh * 2] * outsc, acc[mt][nt][rh * 2 + 1] * outsc);
                *reinterpret_cast<uint32_t*>(
                    &Cout[(((size_t)(b * HH + h)) * SS + s) * DK + col]) = v;
            }
        }
    }
}

// ---------------------------------------------------------------------------
// Output projection GEMM: A = g_Ct (half), B = Wo (fp32->half), out fp32.
// ---------------------------------------------------------------------------
__global__ __launch_bounds__(256, 2) void out_gemm_t(
    const float* __restrict__ Wo, float* __restrict__ out)
{
    __shared__ __align__(16) __half As[128 * APH];
    __shared__ __align__(16) __half Bs[32 * BPH];

    const int m0 = blockIdx.x * 128;
    const int n0 = blockIdx.y * 64;

    const int tid  = threadIdx.x;
    const int warp = tid >> 5;
    const int lane = tid & 31;
    const int g    = lane >> 2;
    const int tig  = lane & 3;
    const int wm   = (warp & 3) * 32;
    const int wn   = (warp >> 2) * 32;

    const uint32_t as_b = smem_u32(As);
    const uint32_t bs_b = smem_u32(Bs);
    const int rA  = (lane & 7) + ((lane >> 3) & 1) * 8;
    const int cA  = ((lane >> 4) & 1) * 8;
    const int rBt = (lane & 7) + ((lane >> 3) & 1) * 8;
    const int cBt = ((lane >> 4) & 1) * 8;

    const int am = tid & 127;
    const int akh = (tid >> 7) * 16;
    const int bkr = tid >> 3;
    const int bn8 = (tid & 7) * 8;

    float acc[2][4][4];
    #pragma unroll
    for (int i = 0; i < 2; ++i)
        #pragma unroll
        for (int j = 0; j < 4; ++j)
            #pragma unroll
            for (int l2 = 0; l2 < 4; ++l2) acc[i][j][l2] = 0.f;

    uint4 ah[2];
    float4 bv[2];
    ah[0] = *reinterpret_cast<const uint4*>(&g_Ct[(size_t)(m0 + am) * DD + akh]);
    ah[1] = *reinterpret_cast<const uint4*>(&g_Ct[(size_t)(m0 + am) * DD + akh + 8]);
    #pragma unroll
    for (int j = 0; j < 2; ++j)
        bv[j] = *reinterpret_cast<const float4*>(&Wo[(size_t)bkr * DD + n0 + bn8 + 4 * j]);

    for (int k0 = 0; k0 < DD; k0 += 32) {
        {
            *reinterpret_cast<uint4*>(&As[am * APH + akh])     = ah[0];
            *reinterpret_cast<uint4*>(&As[am * APH + akh + 8]) = ah[1];
            uint32_t bw[4];
            bw[0] = h2pack(bv[0].x, bv[0].y);
            bw[1] = h2pack(bv[0].z, bv[0].w);
            bw[2] = h2pack(bv[1].x, bv[1].y);
            bw[3] = h2pack(bv[1].z, bv[1].w);
            *reinterpret_cast<uint4*>(&Bs[bkr * BPH + bn8]) = *reinterpret_cast<uint4*>(bw);
        }
        __syncthreads();

        if (k0 + 32 < DD) {
            ah[0] = *reinterpret_cast<const uint4*>(&g_Ct[(size_t)(m0 + am) * DD + k0 + 32 + akh]);
            ah[1] = *reinterpret_cast<const uint4*>(&g_Ct[(size_t)(m0 + am) * DD + k0 + 32 + akh + 8]);
            #pragma unroll
            for (int j = 0; j < 2; ++j)
                bv[j] = *reinterpret_cast<const float4*>(&Wo[(size_t)(k0 + 32 + bkr) * DD + n0 + bn8 + 4 * j]);
        }

        #pragma unroll
        for (int kc = 0; kc < 2; ++kc) {
            uint32_t af[2][4];
            #pragma unroll
            for (int mt = 0; mt < 2; ++mt)
                ldsm4(af[mt], as_b + ((wm + mt * 16 + rA) * APH + kc * 16 + cA) * 2);
            uint32_t bf[4];
            ldsm4t(bf, bs_b + ((kc * 16 + rBt) * BPH + wn + cBt) * 2);
            uint32_t bf2[4];
            ldsm4t(bf2, bs_b + ((kc * 16 + rBt) * BPH + wn + 16 + cBt) * 2);
            #pragma unroll
            for (int mt = 0; mt < 2; ++mt) {
                mma_f16(acc[mt][0], af[mt], bf[0],  bf[1]);
                mma_f16(acc[mt][1], af[mt], bf[2],  bf[3]);
                mma_f16(acc[mt][2], af[mt], bf2[0], bf2[1]);
                mma_f16(acc[mt][3], af[mt], bf2[2], bf2[3]);
            }
        }
        __syncthreads();
    }

    #pragma unroll
    for (int mt = 0; mt < 2; ++mt) {
        #pragma unroll
        for (int nt = 0; nt < 4; ++nt) {
            const int col = n0 + wn + nt * 8 + 2 * tig;
            #pragma unroll
            for (int rh = 0; rh < 2; ++rh) {
                const int m = m0 + wm + mt * 16 + g + rh * 8;
                float2 v = make_float2(acc[mt][nt][rh * 2], acc[mt][nt][rh * 2 + 1]);
                *reinterpret_cast<float2*>(&out[(size_t)m * DD + col]) = v;
            }
        }
    }
}

// ---------------------------------------------------------------------------
// Flash attention, fp16 mma.
//   CTA = 128 q-rows of one (b,h); 256 threads / 8 warps; warp = 16 q rows.
//   QP[q=128][72]: Q staging then P (warp-local rows). Ks[s=64][72], Vs[s=64][72].
//   S:  A = Q (non-trans), B = K rows=s (non-trans, [n=s][k=d]).
//   PV: A = P (non-trans), B = V rows=s (TRANS, [k=s][n=d]).
// ---------------------------------------------------------------------------
#define FPH 72

__global__ __launch_bounds__(256, 2) void flash_attn_t()
{
    __shared__ __align__(16) __half QP[128 * FPH];
    __shared__ __align__(16) __half Ks[64 * FPH];
    __shared__ __align__(16) __half Vs[64 * FPH];

    const int tid  = threadIdx.x;
    const int w    = tid >> 5;
    const int lane = tid & 31;
    const int g    = lane >> 2;
    const int tig  = lane & 3;
    const int wr   = w * 16;

    const uint32_t qp_b = smem_u32(QP);
    const uint32_t ks_b = smem_u32(Ks);
    const uint32_t vs_b = smem_u32(Vs);
    const int rA  = (lane & 7) + ((lane >> 3) & 1) * 8;
    const int cA  = ((lane >> 4) & 1) * 8;
    const int rBn = ((lane >> 4) & 1) * 8 + (lane & 7);   // non-trans B ([n][k])
    const int cBn = ((lane >> 3) & 1) * 8;
    const int rBt = (lane & 7) + ((lane >> 3) & 1) * 8;   // trans B ([k][n])
    const int cBt = ((lane >> 4) & 1) * 8;

    const int q0 = blockIdx.x * 128;
    const int bh = blockIdx.y;
    const __half* Qp = g_Q + (size_t)bh * SS * DK;
    const __half* Kp = g_K + (size_t)bh * SS * DK;
    const __half* Vp = g_V + (size_t)bh * SS * DK;

    // ---- stage Q (already scaled in qkv epilogue): pure copy ----
    {
        const int qr = tid >> 1;
        const int qc = (tid & 1) * 32;
        const uint4* src = reinterpret_cast<const uint4*>(Qp + (size_t)(q0 + qr) * DK + qc);
        #pragma unroll
        for (int j = 0; j < 4; ++j)
            *reinterpret_cast<uint4*>(&QP[qr * FPH + qc + 8 * j]) = src[j];
    }
    __syncthreads();

    uint32_t qf[4][4];
    #pragma unroll
    for (int kc = 0; kc < 4; ++kc)
        ldsm4(qf[kc], qp_b + ((wr + rA) * FPH + kc * 16 + cA) * 2);

    float of[8][4];
    #pragma unroll
    for (int nt = 0; nt < 8; ++nt)
        #pragma unroll
        for (int i = 0; i < 4; ++i) of[nt][i] = 0.f;
    float mA = -1e30f, mB = -1e30f, lA = 0.f, lB = 0.f;

    const int ls = tid >> 2;           // s row
    const int lc = (tid & 3) * 16;     // 16-half chunk

    for (int kt = 0; kt < SS; kt += 64) {
        __syncthreads();

        // ---- stage K and V tiles (pure copies) ----
        {
            const uint4* ksrc = reinterpret_cast<const uint4*>(Kp + (size_t)(kt + ls) * DK + lc);
            const uint4* vsrc = reinterpret_cast<const uint4*>(Vp + (size_t)(kt + ls) * DK + lc);
            *reinterpret_cast<uint4*>(&Ks[ls * FPH + lc])     = ksrc[0];
            *reinterpret_cast<uint4*>(&Ks[ls * FPH + lc + 8]) = ksrc[1];
            *reinterpret_cast<uint4*>(&Vs[ls * FPH + lc])     = vsrc[0];
            *reinterpret_cast<uint4*>(&Vs[ls * FPH + lc + 8]) = vsrc[1];
        }
        __syncthreads();

        // ---- S = Q K^T ----
        float sf[8][4];
        #pragma unroll
        for (int nt = 0; nt < 8; ++nt)
            #pragma unroll
            for (int i = 0; i < 4; ++i) sf[nt][i] = 0.f;
        #pragma unroll
        for (int kc = 0; kc < 4; ++kc) {
            #pragma unroll
            for (int ntp = 0; ntp < 4; ++ntp) {
                uint32_t bf[4];
                ldsm4(bf, ks_b + ((ntp * 16 + rBn) * FPH + kc * 16 + cBn) * 2);
                mma_f16(sf[2 * ntp + 0], qf[kc], bf[0], bf[1]);
                mma_f16(sf[2 * ntp + 1], qf[kc], bf[2], bf[3]);
            }
        }

        // ---- online softmax (rows wr+g, wr+g+8), base-2 domain ----
        float mtA = sf[0][0], mtB = sf[0][2];
        #pragma unroll
        for (int nt = 0; nt < 8; ++nt) {
            mtA = fmaxf(mtA, fmaxf(sf[nt][0], sf[nt][1]));
            mtB = fmaxf(mtB, fmaxf(sf[nt][2], sf[nt][3]));
        }
        mtA = fmaxf(mtA, __shfl_xor_sync(0xffffffffu, mtA, 1));
        mtA = fmaxf(mtA, __shfl_xor_sync(0xffffffffu, mtA, 2));
        mtB = fmaxf(mtB, __shfl_xor_sync(0xffffffffu, mtB, 1));
        mtB = fmaxf(mtB, __shfl_xor_sync(0xffffffffu, mtB, 2));

        const float mnA = fmaxf(mA, mtA);
        const float mnB = fmaxf(mB, mtB);
        const float corA = fast_ex2(mA - mnA);
        const float corB = fast_ex2(mB - mnB);

        float sumA = 0.f, sumB = 0.f;
        #pragma unroll
        for (int nt = 0; nt < 8; ++nt) {
            sf[nt][0] = fast_ex2(sf[nt][0] - mnA);
            sf[nt][1] = fast_ex2(sf[nt][1] - mnA);
            sf[nt][2] = fast_ex2(sf[nt][2] - mnB);
            sf[nt][3] = fast_ex2(sf[nt][3] - mnB);
            sumA += sf[nt][0] + sf[nt][1];
            sumB += sf[nt][2] + sf[nt][3];
        }
        sumA += __shfl_xor_sync(0xffffffffu, sumA, 1);
        sumA += __shfl_xor_sync(0xffffffffu, sumA, 2);
        sumB += __shfl_xor_sync(0xffffffffu, sumB, 1);
        sumB += __shfl_xor_sync(0xffffffffu, sumB, 2);

        lA = lA * corA + sumA; mA = mnA;
        lB = lB * corB + sumB; mB = mnB;
        #pragma unroll
        for (int nt = 0; nt < 8; ++nt) {
            of[nt][0] *= corA; of[nt][1] *= corA;
            of[nt][2] *= corB; of[nt][3] *= corB;
        }

        // ---- P (half2) -> QP rows wr..wr+15 (warp-local) ----
        #pragma unroll
        for (int nt = 0; nt < 8; ++nt) {
            *reinterpret_cast<uint32_t*>(&QP[(wr + g)     * FPH + nt * 8 + 2 * tig]) =
                h2pack(sf[nt][0], sf[nt][1]);
            *reinterpret_cast<uint32_t*>(&QP[(wr + g + 8) * FPH + nt * 8 + 2 * tig]) =
                h2pack(sf[nt][2], sf[nt][3]);
        }
        __syncwarp();

        // ---- O += P V ----
        uint32_t pf[4][4];
        #pragma unroll
        for (int kc = 0; kc < 4; ++kc)
            ldsm4(pf[kc], qp_b + ((wr + rA) * FPH + kc * 16 + cA) * 2);
        #pragma unroll
        for (int kc = 0; kc < 4; ++kc) {
            #pragma unroll
            for (int ntp = 0; ntp < 4; ++ntp) {
                uint32_t bf[4];
                ldsm4t(bf, vs_b + ((kc * 16 + rBt) * FPH + ntp * 16 + cBt) * 2);
                mma_f16(of[2 * ntp + 0], pf[kc], bf[0], bf[1]);
                mma_f16(of[2 * ntp + 1], pf[kc], bf[2], bf[3]);
            }
        }
    }

    // ---- epilogue: g_Ct[b*S + q, h*64 + d] (half2) ----
    {
        const float invA = 1.f / lA;
        const float invB = 1.f / lB;
        const int b = bh >> 4, h = bh & 15;
        const size_t rowA = (size_t)b * SS + q0 + wr + g;
        const size_t rowB = rowA + 8;
        #pragma unroll
        for (int nt = 0; nt < 8; ++nt) {
            const int col = h * 64 + nt * 8 + 2 * tig;
            *reinterpret_cast<uint32_t*>(&g_Ct[rowA * DD + col]) =
                h2pack(of[nt][0] * invA, of[nt][1] * invA);
            *reinterpret_cast<uint32_t*>(&g_Ct[rowB * DD + col]) =
                h2pack(of[nt][2] * invB, of[nt][3] * invB);
        }
    }
}

extern "C" void kernel_launch(void* const* d_in, const int* in_sizes, int n_in,
                              void* d_out, int out_size)
{
    const float* x  = (const float*)d_in[0];
    const float* Wq = (const float*)d_in[1];
    const float* Wk = (const float*)d_in[2];
    const float* Wv = (const float*)d_in[3];
    const float* Wo = (const float*)d_in[4];
    float* out = (float*)d_out;

    (void)in_sizes; (void)n_in; (void)out_size;

    qkv_gemm_t<<<dim3(M_TOT / 128, HH, 3), 256>>>(x, Wq, Wk, Wv);
    flash_attn_t<<<dim3(SS / 128, BB * HH), 256>>>();
    out_gemm_t<<<dim3(M_TOT / 128, DD / 64), 256>>>(Wo, out);
}

// round 7
// speedup vs baseline: 3.9539x; 1.5730x over previous
#include <cuda_runtime.h>
#include <cuda_fp16.h>
#include <cstdint>

#define BB 4
#define SS 2048
#define DD 1024
#define HH 16
#define DK 64
#define M_TOT (BB*SS)   // 8192

// fp16 scratch (allocation-free rule: __device__ globals)
__device__ __half g_Q[BB*HH*SS*DK];
__device__ __half g_K[BB*HH*SS*DK];
__device__ __half g_V[BB*HH*SS*DK];
__device__ __half g_Ct[(size_t)M_TOT*DD];
__device__ __half g_Xh[(size_t)M_TOT*DD];        // x in fp16
__device__ __half g_Wh[3*(size_t)DD*DD];         // Wq|Wk|Wv fused: [z][d][h*64+k]
__device__ __half g_Woh[(size_t)DD*DD];          // Wo fp16

#define QSC_F (0.125f * 1.4426950408889634f)

// ---------------------------------------------------------------------------
// helpers
// ---------------------------------------------------------------------------
__device__ __forceinline__ float fast_ex2(float x) {
    float y;
    asm("ex2.approx.ftz.f32 %0, %1;" : "=f"(y) : "f"(x));
    return y;
}

__device__ __forceinline__ void mma_f16(float* c, const uint32_t* a, uint32_t b0, uint32_t b1) {
    asm volatile(
        "mma.sync.aligned.m16n8k16.row.col.f32.f16.f16.f32 "
        "{%0,%1,%2,%3}, {%4,%5,%6,%7}, {%8,%9}, {%0,%1,%2,%3};"
        : "+f"(c[0]), "+f"(c[1]), "+f"(c[2]), "+f"(c[3])
        : "r"(a[0]), "r"(a[1]), "r"(a[2]), "r"(a[3]), "r"(b0), "r"(b1));
}

__device__ __forceinline__ void ldsm4(uint32_t* r, uint32_t addr) {
    asm volatile("ldmatrix.sync.aligned.m8n8.x4.shared.b16 {%0,%1,%2,%3}, [%4];"
        : "=r"(r[0]), "=r"(r[1]), "=r"(r[2]), "=r"(r[3]) : "r"(addr));
}
__device__ __forceinline__ void ldsm4t(uint32_t* r, uint32_t addr) {
    asm volatile("ldmatrix.sync.aligned.m8n8.x4.trans.shared.b16 {%0,%1,%2,%3}, [%4];"
        : "=r"(r[0]), "=r"(r[1]), "=r"(r[2]), "=r"(r[3]) : "r"(addr));
}

__device__ __forceinline__ uint32_t smem_u32(const void* p) {
    uint32_t a;
    asm("{ .reg .u64 t; cvta.to.shared.u64 t, %1; cvt.u32.u64 %0, t; }" : "=r"(a) : "l"(p));
    return a;
}

__device__ __forceinline__ uint32_t h2pack(float a, float b) {
    __half2 h = __floats2half2_rn(a, b);
    return *reinterpret_cast<uint32_t*>(&h);
}

// ---------------------------------------------------------------------------
// Pre-convert: x -> fp16; Wq/Wk/Wv -> fused fp16 [z][d][h*64+k]; Wo -> fp16.
// ---------------------------------------------------------------------------
__global__ __launch_bounds__(256) void conv_x(const float* __restrict__ x)
{
    const size_t i = ((size_t)blockIdx.x * 256 + threadIdx.x) * 8;
    float4 a = *reinterpret_cast<const float4*>(x + i);
    float4 b = *reinterpret_cast<const float4*>(x + i + 4);
    uint4 t;
    t.x = h2pack(a.x, a.y); t.y = h2pack(a.z, a.w);
    t.z = h2pack(b.x, b.y); t.w = h2pack(b.z, b.w);
    *reinterpret_cast<uint4*>(g_Xh + i) = t;
}

__global__ __launch_bounds__(256) void conv_w(
    const float* __restrict__ Wq, const float* __restrict__ Wk,
    const float* __restrict__ Wv, const float* __restrict__ Wo)
{
    const size_t gi = ((size_t)blockIdx.x * 256 + threadIdx.x) * 2;
    const int z = (int)(gi >> 20);             // 1M elements per matrix
    const size_t i = gi & 1048575u;
    if (z < 3) {
        const float* src = (z == 0) ? Wq : (z == 1) ? Wk : Wv;
        float2 v = *reinterpret_cast<const float2*>(src + i);
        const int h = (int)(i >> 16);          // [h][d][k]
        const int d = (int)((i >> 6) & 1023);
        const int k = (int)(i & 63);
        *reinterpret_cast<uint32_t*>(&g_Wh[(size_t)z * DD * DD + (size_t)d * DD + h * 64 + k]) =
            h2pack(v.x, v.y);
    } else {
        float2 v = *reinterpret_cast<const float2*>(Wo + i);
        *reinterpret_cast<uint32_t*>(&g_Woh[i]) = h2pack(v.x, v.y);
    }
}

// ---------------------------------------------------------------------------
// Shared fp16 GEMM body: C[128 x 128] tile, BK=32, 256 thr, warp 64x32 (2m x 4n).
// A[m][k] pitch 40 halfs; B[k][n] pitch 136 halfs (ldsm.trans for B frags).
// ---------------------------------------------------------------------------
#define APH 40
#define BPH 136

struct GemmFrags { float acc[4][4][4]; };

// epilogue modes: 0 = qkv (write g_Q/K/V, [B,H,S,64], scale for z==0), 1 = out fp32
__global__ __launch_bounds__(256, 2) void qkv_gemm_t()
{
    __shared__ __align__(16) __half As[128 * APH];
    __shared__ __align__(16) __half Bs[32 * BPH];

    const int m0 = blockIdx.x * 128;
    const int zy = blockIdx.y;            // z*8 + nb
    const int z  = zy >> 3;
    const int n0 = (zy & 7) * 128;
    const __half* Asrc = g_Xh;
    const __half* Bsrc = g_Wh + (size_t)z * DD * DD;
    __half* Cout = (z == 0) ? g_Q : (z == 1) ? g_K : g_V;
    const float outsc = (z == 0) ? QSC_F : 1.0f;

    const int tid  = threadIdx.x;
    const int warp = tid >> 5;
    const int lane = tid & 31;
    const int g    = lane >> 2;
    const int tig  = lane & 3;
    const int wm   = (warp & 1) * 64;
    const int wn   = (warp >> 1) * 32;

    const uint32_t as_b = smem_u32(As);
    const uint32_t bs_b = smem_u32(Bs);
    const int rA  = (lane & 7) + ((lane >> 3) & 1) * 8;
    const int cA  = ((lane >> 4) & 1) * 8;
    const int rBt = (lane & 7) + ((lane >> 3) & 1) * 8;
    const int cBt = ((lane >> 4) & 1) * 8;

    // A loader: row = tid&127, 16 halfs at (tid>>7)*16
    const int am  = tid & 127;
    const int akh = (tid >> 7) * 16;
    // B loader: row k = tid>>3 (0..31), two 8-half chunks at (tid&7)*8 and +64
    const int bkr = tid >> 3;
    const int bc0 = (tid & 7) * 8;

    float acc[4][4][4];
    #pragma unroll
    for (int i = 0; i < 4; ++i)
        #pragma unroll
        for (int j = 0; j < 4; ++j)
            #pragma unroll
            for (int l2 = 0; l2 < 4; ++l2) acc[i][j][l2] = 0.f;

    uint4 ap0, ap1, bp0, bp1;
    ap0 = *reinterpret_cast<const uint4*>(Asrc + (size_t)(m0 + am) * DD + akh);
    ap1 = *reinterpret_cast<const uint4*>(Asrc + (size_t)(m0 + am) * DD + akh + 8);
    bp0 = *reinterpret_cast<const uint4*>(Bsrc + (size_t)bkr * DD + n0 + bc0);
    bp1 = *reinterpret_cast<const uint4*>(Bsrc + (size_t)bkr * DD + n0 + bc0 + 64);

    for (int k0 = 0; k0 < DD; k0 += 32) {
        *reinterpret_cast<uint4*>(&As[am * APH + akh])      = ap0;
        *reinterpret_cast<uint4*>(&As[am * APH + akh + 8])  = ap1;
        *reinterpret_cast<uint4*>(&Bs[bkr * BPH + bc0])     = bp0;
        *reinterpret_cast<uint4*>(&Bs[bkr * BPH + bc0 + 64])= bp1;
        __syncthreads();

        if (k0 + 32 < DD) {
            ap0 = *reinterpret_cast<const uint4*>(Asrc + (size_t)(m0 + am) * DD + k0 + 32 + akh);
            ap1 = *reinterpret_cast<const uint4*>(Asrc + (size_t)(m0 + am) * DD + k0 + 32 + akh + 8);
            bp0 = *reinterpret_cast<const uint4*>(Bsrc + (size_t)(k0 + 32 + bkr) * DD + n0 + bc0);
            bp1 = *reinterpret_cast<const uint4*>(Bsrc + (size_t)(k0 + 32 + bkr) * DD + n0 + bc0 + 64);
        }

        #pragma unroll
        for (int kc = 0; kc < 2; ++kc) {
            uint32_t af[4][4];
            #pragma unroll
            for (int mt = 0; mt < 4; ++mt)
                ldsm4(af[mt], as_b + ((wm + mt * 16 + rA) * APH + kc * 16 + cA) * 2);
            uint32_t bf[2][4];
            ldsm4t(bf[0], bs_b + ((kc * 16 + rBt) * BPH + wn + cBt) * 2);
            ldsm4t(bf[1], bs_b + ((kc * 16 + rBt) * BPH + wn + 16 + cBt) * 2);
            #pragma unroll
            for (int mt = 0; mt < 4; ++mt) {
                mma_f16(acc[mt][0], af[mt], bf[0][0], bf[0][1]);
                mma_f16(acc[mt][1], af[mt], bf[0][2], bf[0][3]);
                mma_f16(acc[mt][2], af[mt], bf[1][0], bf[1][1]);
                mma_f16(acc[mt][3], af[mt], bf[1][2], bf[1][3]);
            }
        }
        __syncthreads();
    }

    // Epilogue: n_global = n0 + wn + nt*8 + 2*tig -> (h, k); write [B,H,S,64]
    #pragma unroll
    for (int mt = 0; mt < 4; ++mt) {
        #pragma unroll
        for (int nt = 0; nt < 4; ++nt) {
            const int n = n0 + wn + nt * 8 + 2 * tig;
            const int h = n >> 6;
            const int k = n & 63;
            #pragma unroll
            for (int rh = 0; rh < 2; ++rh) {
                const int m = m0 + wm + mt * 16 + g + rh * 8;
                const int b = m >> 11;
                const int s = m & 2047;
                uint32_t v = h2pack(acc[mt][nt][rh * 2] * outsc, acc[mt][nt][rh * 2 + 1] * outsc);
                *reinterpret_cast<uint32_t*>(
                    &Cout[(((size_t)(b * HH + h)) * SS + s) * DK + k]) = v;
            }
        }
    }
}

__global__ __launch_bounds__(256, 2) void out_gemm_t(float* __restrict__ out)
{
    __shared__ __align__(16) __half As[128 * APH];
    __shared__ __align__(16) __half Bs[32 * BPH];

    const int m0 = blockIdx.x * 128;
    const int n0 = blockIdx.y * 128;

    const int tid  = threadIdx.x;
    const int warp = tid >> 5;
    const int lane = tid & 31;
    const int g    = lane >> 2;
    const int tig  = lane & 3;
    const int wm   = (warp & 1) * 64;
    const int wn   = (warp >> 1) * 32;

    const uint32_t as_b = smem_u32(As);
    const uint32_t bs_b = smem_u32(Bs);
    const int rA  = (lane & 7) + ((lane >> 3) & 1) * 8;
    const int cA  = ((lane >> 4) & 1) * 8;
    const int rBt = (lane & 7) + ((lane >> 3) & 1) * 8;
    const int cBt = ((lane >> 4) & 1) * 8;

    const int am  = tid & 127;
    const int akh = (tid >> 7) * 16;
    const int bkr = tid >> 3;
    const int bc0 = (tid & 7) * 8;

    float acc[4][4][4];
    #pragma unroll
    for (int i = 0; i < 4; ++i)
        #pragma unroll
        for (int j = 0; j < 4; ++j)
            #pragma unroll
            for (int l2 = 0; l2 < 4; ++l2) acc[i][j][l2] = 0.f;

    uint4 ap0, ap1, bp0, bp1;
    ap0 = *reinterpret_cast<const uint4*>(g_Ct + (size_t)(m0 + am) * DD + akh);
    ap1 = *reinterpret_cast<const uint4*>(g_Ct + (size_t)(m0 + am) * DD + akh + 8);
    bp0 = *reinterpret_cast<const uint4*>(g_Woh + (size_t)bkr * DD + n0 + bc0);
    bp1 = *reinterpret_cast<const uint4*>(g_Woh + (size_t)bkr * DD + n0 + bc0 + 64);

    for (int k0 = 0; k0 < DD; k0 += 32) {
        *reinterpret_cast<uint4*>(&As[am * APH + akh])      = ap0;
        *reinterpret_cast<uint4*>(&As[am * APH + akh + 8])  = ap1;
        *reinterpret_cast<uint4*>(&Bs[bkr * BPH + bc0])     = bp0;
        *reinterpret_cast<uint4*>(&Bs[bkr * BPH + bc0 + 64])= bp1;
        __syncthreads();

        if (k0 + 32 < DD) {
            ap0 = *reinterpret_cast<const uint4*>(g_Ct + (size_t)(m0 + am) * DD + k0 + 32 + akh);
            ap1 = *reinterpret_cast<const uint4*>(g_Ct + (size_t)(m0 + am) * DD + k0 + 32 + akh + 8);
            bp0 = *reinterpret_cast<const uint4*>(g_Woh + (size_t)(k0 + 32 + bkr) * DD + n0 + bc0);
            bp1 = *reinterpret_cast<const uint4*>(g_Woh + (size_t)(k0 + 32 + bkr) * DD + n0 + bc0 + 64);
        }

        #pragma unroll
        for (int kc = 0; kc < 2; ++kc) {
            uint32_t af[4][4];
            #pragma unroll
            for (int mt = 0; mt < 4; ++mt)
                ldsm4(af[mt], as_b + ((wm + mt * 16 + rA) * APH + kc * 16 + cA) * 2);
            uint32_t bf[2][4];
            ldsm4t(bf[0], bs_b + ((kc * 16 + rBt) * BPH + wn + cBt) * 2);
            ldsm4t(bf[1], bs_b + ((kc * 16 + rBt) * BPH + wn + 16 + cBt) * 2);
            #pragma unroll
            for (int mt = 0; mt < 4; ++mt) {
                mma_f16(acc[mt][0], af[mt], bf[0][0], bf[0][1]);
                mma_f16(acc[mt][1], af[mt], bf[0][2], bf[0][3]);
                mma_f16(acc[mt][2], af[mt], bf[1][0], bf[1][1]);
                mma_f16(acc[mt][3], af[mt], bf[1][2], bf[1][3]);
            }
        }
        __syncthreads();
    }

    #pragma unroll
    for (int mt = 0; mt < 4; ++mt) {
        #pragma unroll
        for (int nt = 0; nt < 4; ++nt) {
            const int col = n0 + wn + nt * 8 + 2 * tig;
            #pragma unroll
            for (int rh = 0; rh < 2; ++rh) {
                const int m = m0 + wm + mt * 16 + g + rh * 8;
                float2 v = make_float2(acc[mt][nt][rh * 2], acc[mt][nt][rh * 2 + 1]);
                *reinterpret_cast<float2*>(&out[(size_t)m * DD + col]) = v;
            }
        }
    }
}

// ---------------------------------------------------------------------------
// Flash attention, fp16 mma (unchanged from R6).
// ---------------------------------------------------------------------------
#define FPH 72

__global__ __launch_bounds__(256, 2) void flash_attn_t()
{
    __shared__ __align__(16) __half QP[128 * FPH];
    __shared__ __align__(16) __half Ks[64 * FPH];
    __shared__ __align__(16) __half Vs[64 * FPH];

    const int tid  = threadIdx.x;
    const int w    = tid >> 5;
    const int lane = tid & 31;
    const int g    = lane >> 2;
    const int tig  = lane & 3;
    const int wr   = w * 16;

    const uint32_t qp_b = smem_u32(QP);
    const uint32_t ks_b = smem_u32(Ks);
    const uint32_t vs_b = smem_u32(Vs);
    const int rA  = (lane & 7) + ((lane >> 3) & 1) * 8;
    const int cA  = ((lane >> 4) & 1) * 8;
    const int rBn = ((lane >> 4) & 1) * 8 + (lane & 7);
    const int cBn = ((lane >> 3) & 1) * 8;
    const int rBt = (lane & 7) + ((lane >> 3) & 1) * 8;
    const int cBt = ((lane >> 4) & 1) * 8;

    const int q0 = blockIdx.x * 128;
    const int bh = blockIdx.y;
    const __half* Qp = g_Q + (size_t)bh * SS * DK;
    const __half* Kp = g_K + (size_t)bh * SS * DK;
    const __half* Vp = g_V + (size_t)bh * SS * DK;

    {
        const int qr = tid >> 1;
        const int qc = (tid & 1) * 32;
        const uint4* src = reinterpret_cast<const uint4*>(Qp + (size_t)(q0 + qr) * DK + qc);
        #pragma unroll
        for (int j = 0; j < 4; ++j)
            *reinterpret_cast<uint4*>(&QP[qr * FPH + qc + 8 * j]) = src[j];
    }
    __syncthreads();

    uint32_t qf[4][4];
    #pragma unroll
    for (int kc = 0; kc < 4; ++kc)
        ldsm4(qf[kc], qp_b + ((wr + rA) * FPH + kc * 16 + cA) * 2);

    float of[8][4];
    #pragma unroll
    for (int nt = 0; nt < 8; ++nt)
        #pragma unroll
        for (int i = 0; i < 4; ++i) of[nt][i] = 0.f;
    float mA = -1e30f, mB = -1e30f, lA = 0.f, lB = 0.f;

    const int ls = tid >> 2;
    const int lc = (tid & 3) * 16;

    for (int kt = 0; kt < SS; kt += 64) {
        __syncthreads();

        {
            const uint4* ksrc = reinterpret_cast<const uint4*>(Kp + (size_t)(kt + ls) * DK + lc);
            const uint4* vsrc = reinterpret_cast<const uint4*>(Vp + (size_t)(kt + ls) * DK + lc);
            *reinterpret_cast<uint4*>(&Ks[ls * FPH + lc])     = ksrc[0];
            *reinterpret_cast<uint4*>(&Ks[ls * FPH + lc + 8]) = ksrc[1];
            *reinterpret_cast<uint4*>(&Vs[ls * FPH + lc])     = vsrc[0];
            *reinterpret_cast<uint4*>(&Vs[ls * FPH + lc + 8]) = vsrc[1];
        }
        __syncthreads();

        float sf[8][4];
        #pragma unroll
        for (int nt = 0; nt < 8; ++nt)
            #pragma unroll
            for (int i = 0; i < 4; ++i) sf[nt][i] = 0.f;
        #pragma unroll
        for (int kc = 0; kc < 4; ++kc) {
            #pragma unroll
            for (int ntp = 0; ntp < 4; ++ntp) {
                uint32_t bf[4];
                ldsm4(bf, ks_b + ((ntp * 16 + rBn) * FPH + kc * 16 + cBn) * 2);
                mma_f16(sf[2 * ntp + 0], qf[kc], bf[0], bf[1]);
                mma_f16(sf[2 * ntp + 1], qf[kc], bf[2], bf[3]);
            }
        }

        float mtA = sf[0][0], mtB = sf[0][2];
        #pragma unroll
        for (int nt = 0; nt < 8; ++nt) {
            mtA = fmaxf(mtA, fmaxf(sf[nt][0], sf[nt][1]));
            mtB = fmaxf(mtB, fmaxf(sf[nt][2], sf[nt][3]));
        }
        mtA = fmaxf(mtA, __shfl_xor_sync(0xffffffffu, mtA, 1));
        mtA = fmaxf(mtA, __shfl_xor_sync(0xffffffffu, mtA, 2));
        mtB = fmaxf(mtB, __shfl_xor_sync(0xffffffffu, mtB, 1));
        mtB = fmaxf(mtB, __shfl_xor_sync(0xffffffffu, mtB, 2));

        const float mnA = fmaxf(mA, mtA);
        const float mnB = fmaxf(mB, mtB);
        const float corA = fast_ex2(mA - mnA);
        const float corB = fast_ex2(mB - mnB);

        float sumA = 0.f, sumB = 0.f;
        #pragma unroll
        for (int nt = 0; nt < 8; ++nt) {
            sf[nt][0] = fast_ex2(sf[nt][0] - mnA);
            sf[nt][1] = fast_ex2(sf[nt][1] - mnA);
            sf[nt][2] = fast_ex2(sf[nt][2] - mnB);
            sf[nt][3] = fast_ex2(sf[nt][3] - mnB);
            sumA += sf[nt][0] + sf[nt][1];
            sumB += sf[nt][2] + sf[nt][3];
        }
        sumA += __shfl_xor_sync(0xffffffffu, sumA, 1);
        sumA += __shfl_xor_sync(0xffffffffu, sumA, 2);
        sumB += __shfl_xor_sync(0xffffffffu, sumB, 1);
        sumB += __shfl_xor_sync(0xffffffffu, sumB, 2);

        lA = lA * corA + sumA; mA = mnA;
        lB = lB * corB + sumB; mB = mnB;
        #pragma unroll
        for (int nt = 0; nt < 8; ++nt) {
            of[nt][0] *= corA; of[nt][1] *= corA;
            of[nt][2] *= corB; of[nt][3] *= corB;
        }

        #pragma unroll
        for (int nt = 0; nt < 8; ++nt) {
            *reinterpret_cast<uint32_t*>(&QP[(wr + g)     * FPH + nt * 8 + 2 * tig]) =
                h2pack(sf[nt][0], sf[nt][1]);
            *reinterpret_cast<uint32_t*>(&QP[(wr + g + 8) * FPH + nt * 8 + 2 * tig]) =
                h2pack(sf[nt][2], sf[nt][3]);
        }
        __syncwarp();

        uint32_t pf[4][4];
        #pragma unroll
        for (int kc = 0; kc < 4; ++kc)
            ldsm4(pf[kc], qp_b + ((wr + rA) * FPH + kc * 16 + cA) * 2);
        #pragma unroll
        for (int kc = 0; kc < 4; ++kc) {
            #pragma unroll
            for (int ntp = 0; ntp < 4; ++ntp) {
                uint32_t bf[4];
                ldsm4t(bf, vs_b + ((kc * 16 + rBt) * FPH + ntp * 16 + cBt) * 2);
                mma_f16(of[2 * ntp + 0], pf[kc], bf[0], bf[1]);
                mma_f16(of[2 * ntp + 1], pf[kc], bf[2], bf[3]);
            }
        }
    }

    {
        const float invA = 1.f / lA;
        const float invB = 1.f / lB;
        const int b = bh >> 4, h = bh & 15;
        const size_t rowA = (size_t)b * SS + q0 + wr + g;
        const size_t rowB = rowA + 8;
        #pragma unroll
        for (int nt = 0; nt < 8; ++nt) {
            const int col = h * 64 + nt * 8 + 2 * tig;
            *reinterpret_cast<uint32_t*>(&g_Ct[rowA * DD + col]) =
                h2pack(of[nt][0] * invA, of[nt][1] * invA);
            *reinterpret_cast<uint32_t*>(&g_Ct[rowB * DD + col]) =
                h2pack(of[nt][2] * invB, of[nt][3] * invB);
        }
    }
}

extern "C" void kernel_launch(void* const* d_in, const int* in_sizes, int n_in,
                              void* d_out, int out_size)
{
    const float* x  = (const float*)d_in[0];
    const float* Wq = (const float*)d_in[1];
    const float* Wk = (const float*)d_in[2];
    const float* Wv = (const float*)d_in[3];
    const float* Wo = (const float*)d_in[4];
    float* out = (float*)d_out;

    (void)in_sizes; (void)n_in; (void)out_size;

    conv_x<<<(M_TOT * DD) / (256 * 8), 256>>>(x);
    conv_w<<<(4 * DD * DD) / (256 * 2), 256>>>(Wq, Wk, Wv, Wo);
    qkv_gemm_t<<<dim3(M_TOT / 128, 24), 256>>>();
    flash_attn_t<<<dim3(SS / 128, BB * HH), 256>>>();
    out_gemm_t<<<dim3(M_TOT / 128, DD / 128), 256>>>(out);
}

// round 8
// speedup vs baseline: 4.3411x; 1.0979x over previous
#include <cuda_runtime.h>
#include <cuda_fp16.h>
#include <cstdint>

#define BB 4
#define SS 2048
#define DD 1024
#define HH 16
#define DK 64
#define M_TOT (BB*SS)   // 8192

// fp16 scratch (allocation-free rule: __device__ globals)
__device__ __half g_Q[BB*HH*SS*DK];
__device__ __half g_K[BB*HH*SS*DK];
__device__ __half g_V[BB*HH*SS*DK];
__device__ __half g_Ct[(size_t)M_TOT*DD];
__device__ __half g_Xh[(size_t)M_TOT*DD];
__device__ __half g_Wh[3*(size_t)DD*DD];         // Wq|Wk|Wv fused: [z][d][h*64+k]
__device__ __half g_Woh[(size_t)DD*DD];

#define QSC_F (0.125f * 1.4426950408889634f)

// ---------------------------------------------------------------------------
// helpers
// ---------------------------------------------------------------------------
__device__ __forceinline__ float fast_ex2(float x) {
    float y;
    asm("ex2.approx.ftz.f32 %0, %1;" : "=f"(y) : "f"(x));
    return y;
}

__device__ __forceinline__ void mma_f16(float* c, const uint32_t* a, uint32_t b0, uint32_t b1) {
    asm volatile(
        "mma.sync.aligned.m16n8k16.row.col.f32.f16.f16.f32 "
        "{%0,%1,%2,%3}, {%4,%5,%6,%7}, {%8,%9}, {%0,%1,%2,%3};"
        : "+f"(c[0]), "+f"(c[1]), "+f"(c[2]), "+f"(c[3])
        : "r"(a[0]), "r"(a[1]), "r"(a[2]), "r"(a[3]), "r"(b0), "r"(b1));
}

__device__ __forceinline__ void ldsm4(uint32_t* r, uint32_t addr) {
    asm volatile("ldmatrix.sync.aligned.m8n8.x4.shared.b16 {%0,%1,%2,%3}, [%4];"
        : "=r"(r[0]), "=r"(r[1]), "=r"(r[2]), "=r"(r[3]) : "r"(addr));
}
__device__ __forceinline__ void ldsm4t(uint32_t* r, uint32_t addr) {
    asm volatile("ldmatrix.sync.aligned.m8n8.x4.trans.shared.b16 {%0,%1,%2,%3}, [%4];"
        : "=r"(r[0]), "=r"(r[1]), "=r"(r[2]), "=r"(r[3]) : "r"(addr));
}

__device__ __forceinline__ uint32_t smem_u32(const void* p) {
    uint32_t a;
    asm("{ .reg .u64 t; cvta.to.shared.u64 t, %1; cvt.u32.u64 %0, t; }" : "=r"(a) : "l"(p));
    return a;
}

__device__ __forceinline__ uint32_t h2pack(float a, float b) {
    __half2 h = __floats2half2_rn(a, b);
    return *reinterpret_cast<uint32_t*>(&h);
}

#define CP16(dst, src) \
    asm volatile("cp.async.cg.shared.global [%0], [%1], 16;" :: "r"(dst), "l"(src))
#define CP_COMMIT() asm volatile("cp.async.commit_group;")
#define CP_WAIT1()  asm volatile("cp.async.wait_group 1;")
#define CP_WAIT0()  asm volatile("cp.async.wait_group 0;")

// ---------------------------------------------------------------------------
// Pre-convert kernels
// ---------------------------------------------------------------------------
__global__ __launch_bounds__(256) void conv_x(const float* __restrict__ x)
{
    const size_t i = ((size_t)blockIdx.x * 256 + threadIdx.x) * 8;
    float4 a = *reinterpret_cast<const float4*>(x + i);
    float4 b = *reinterpret_cast<const float4*>(x + i + 4);
    uint4 t;
    t.x = h2pack(a.x, a.y); t.y = h2pack(a.z, a.w);
    t.z = h2pack(b.x, b.y); t.w = h2pack(b.z, b.w);
    *reinterpret_cast<uint4*>(g_Xh + i) = t;
}

__global__ __launch_bounds__(256) void conv_w(
    const float* __restrict__ Wq, const float* __restrict__ Wk,
    const float* __restrict__ Wv, const float* __restrict__ Wo)
{
    const size_t gi = ((size_t)blockIdx.x * 256 + threadIdx.x) * 2;
    const int z = (int)(gi >> 20);
    const size_t i = gi & 1048575u;
    if (z < 3) {
        const float* src = (z == 0) ? Wq : (z == 1) ? Wk : Wv;
        float2 v = *reinterpret_cast<const float2*>(src + i);
        const int h = (int)(i >> 16);
        const int d = (int)((i >> 6) & 1023);
        const int k = (int)(i & 63);
        *reinterpret_cast<uint32_t*>(&g_Wh[(size_t)z * DD * DD + (size_t)d * DD + h * 64 + k]) =
            h2pack(v.x, v.y);
    } else {
        float2 v = *reinterpret_cast<const float2*>(Wo + i);
        *reinterpret_cast<uint32_t*>(&g_Woh[i]) = h2pack(v.x, v.y);
    }
}

// ---------------------------------------------------------------------------
// fp16 GEMM: C[128x128] tile, BK=32, 256 thr, warp 64x32, cp.async 2-stage.
// A[m][k] pitch 40; B[k][n] pitch 136 (ldsm.trans).
// ---------------------------------------------------------------------------
#define APH 40
#define BPH 136
#define NKIT (DD / 32)

__global__ __launch_bounds__(256, 2) void qkv_gemm_t()
{
    __shared__ __align__(16) __half As[2][128 * APH];
    __shared__ __align__(16) __half Bs[2][32 * BPH];

    const int m0 = blockIdx.x * 128;
    const int zy = blockIdx.y;
    const int z  = zy >> 3;
    const int n0 = (zy & 7) * 128;
    const __half* Asrc = g_Xh;
    const __half* Bsrc = g_Wh + (size_t)z * DD * DD;
    __half* Cout = (z == 0) ? g_Q : (z == 1) ? g_K : g_V;
    const float outsc = (z == 0) ? QSC_F : 1.0f;

    const int tid  = threadIdx.x;
    const int warp = tid >> 5;
    const int lane = tid & 31;
    const int g    = lane >> 2;
    const int tig  = lane & 3;
    const int wm   = (warp & 1) * 64;
    const int wn   = (warp >> 1) * 32;

    const uint32_t as_b0 = smem_u32(As[0]);
    const uint32_t bs_b0 = smem_u32(Bs[0]);
    const int rA  = (lane & 7) + ((lane >> 3) & 1) * 8;
    const int cA  = ((lane >> 4) & 1) * 8;
    const int rBt = (lane & 7) + ((lane >> 3) & 1) * 8;
    const int cBt = ((lane >> 4) & 1) * 8;

    const int am  = tid & 127;
    const int akh = (tid >> 7) * 16;
    const int bkr = tid >> 3;
    const int bc0 = (tid & 7) * 8;

    const uint32_t aDst = as_b0 + (am * APH + akh) * 2;
    const uint32_t bDst = bs_b0 + (bkr * BPH + bc0) * 2;
    const __half* aSrc = Asrc + (size_t)(m0 + am) * DD + akh;
    const __half* bSrc = Bsrc + (size_t)bkr * DD + n0 + bc0;

    float acc[4][4][4];
    #pragma unroll
    for (int i = 0; i < 4; ++i)
        #pragma unroll
        for (int j = 0; j < 4; ++j)
            #pragma unroll
            for (int l2 = 0; l2 < 4; ++l2) acc[i][j][l2] = 0.f;

    // prologue: stage k-tile 0 into buf 0
    CP16(aDst,             aSrc);
    CP16(aDst + 16,        aSrc + 8);
    CP16(bDst,             bSrc);
    CP16(bDst + 128,       bSrc + 64);
    CP_COMMIT();

    for (int it = 0; it < NKIT; ++it) {
        if (it + 1 < NKIT) {
            const uint32_t ab = (uint32_t)((it + 1) & 1) * (128 * APH * 2);
            const uint32_t bb = (uint32_t)((it + 1) & 1) * (32 * BPH * 2);
            const __half* as2 = aSrc + (it + 1) * 32;
            const __half* bs2 = bSrc + (size_t)(it + 1) * 32 * DD;
            CP16(aDst + ab,       as2);
            CP16(aDst + ab + 16,  as2 + 8);
            CP16(bDst + bb,       bs2);
            CP16(bDst + bb + 128, bs2 + 64);
            CP_COMMIT();
            CP_WAIT1();
        } else {
            CP_WAIT0();
        }
        __syncthreads();

        const uint32_t asb = as_b0 + (uint32_t)(it & 1) * (128 * APH * 2);
        const uint32_t bsb = bs_b0 + (uint32_t)(it & 1) * (32 * BPH * 2);
        #pragma unroll
        for (int kc = 0; kc < 2; ++kc) {
            uint32_t af[4][4];
            #pragma unroll
            for (int mt = 0; mt < 4; ++mt)
                ldsm4(af[mt], asb + ((wm + mt * 16 + rA) * APH + kc * 16 + cA) * 2);
            uint32_t bf[2][4];
            ldsm4t(bf[0], bsb + ((kc * 16 + rBt) * BPH + wn + cBt) * 2);
            ldsm4t(bf[1], bsb + ((kc * 16 + rBt) * BPH + wn + 16 + cBt) * 2);
            #pragma unroll
            for (int mt = 0; mt < 4; ++mt) {
                mma_f16(acc[mt][0], af[mt], bf[0][0], bf[0][1]);
                mma_f16(acc[mt][1], af[mt], bf[0][2], bf[0][3]);
                mma_f16(acc[mt][2], af[mt], bf[1][0], bf[1][1]);
                mma_f16(acc[mt][3], af[mt], bf[1][2], bf[1][3]);
            }
        }
        __syncthreads();
    }

    // Epilogue: write [B,H,S,64]
    #pragma unroll
    for (int mt = 0; mt < 4; ++mt) {
        #pragma unroll
        for (int nt = 0; nt < 4; ++nt) {
            const int n = n0 + wn + nt * 8 + 2 * tig;
            const int h = n >> 6;
            const int k = n & 63;
            #pragma unroll
            for (int rh = 0; rh < 2; ++rh) {
                const int m = m0 + wm + mt * 16 + g + rh * 8;
                const int b = m >> 11;
                const int s = m & 2047;
                uint32_t v = h2pack(acc[mt][nt][rh * 2] * outsc, acc[mt][nt][rh * 2 + 1] * outsc);
                *reinterpret_cast<uint32_t*>(
                    &Cout[(((size_t)(b * HH + h)) * SS + s) * DK + k]) = v;
            }
        }
    }
}

__global__ __launch_bounds__(256, 2) void out_gemm_t(float* __restrict__ out)
{
    __shared__ __align__(16) __half As[2][128 * APH];
    __shared__ __align__(16) __half Bs[2][32 * BPH];

    const int m0 = blockIdx.x * 128;
    const int n0 = blockIdx.y * 128;

    const int tid  = threadIdx.x;
    const int warp = tid >> 5;
    const int lane = tid & 31;
    const int g    = lane >> 2;
    const int tig  = lane & 3;
    const int wm   = (warp & 1) * 64;
    const int wn   = (warp >> 1) * 32;

    const uint32_t as_b0 = smem_u32(As[0]);
    const uint32_t bs_b0 = smem_u32(Bs[0]);
    const int rA  = (lane & 7) + ((lane >> 3) & 1) * 8;
    const int cA  = ((lane >> 4) & 1) * 8;
    const int rBt = (lane & 7) + ((lane >> 3) & 1) * 8;
    const int cBt = ((lane >> 4) & 1) * 8;

    const int am  = tid & 127;
    const int akh = (tid >> 7) * 16;
    const int bkr = tid >> 3;
    const int bc0 = (tid & 7) * 8;

    const uint32_t aDst = as_b0 + (am * APH + akh) * 2;
    const uint32_t bDst = bs_b0 + (bkr * BPH + bc0) * 2;
    const __half* aSrc = g_Ct + (size_t)(m0 + am) * DD + akh;
    const __half* bSrc = g_Woh + (size_t)bkr * DD + n0 + bc0;

    float acc[4][4][4];
    #pragma unroll
    for (int i = 0; i < 4; ++i)
        #pragma unroll
        for (int j = 0; j < 4; ++j)
            #pragma unroll
            for (int l2 = 0; l2 < 4; ++l2) acc[i][j][l2] = 0.f;

    CP16(aDst,       aSrc);
    CP16(aDst + 16,  aSrc + 8);
    CP16(bDst,       bSrc);
    CP16(bDst + 128, bSrc + 64);
    CP_COMMIT();

    for (int it = 0; it < NKIT; ++it) {
        if (it + 1 < NKIT) {
            const uint32_t ab = (uint32_t)((it + 1) & 1) * (128 * APH * 2);
            const uint32_t bb = (uint32_t)((it + 1) & 1) * (32 * BPH * 2);
            const __half* as2 = aSrc + (it + 1) * 32;
            const __half* bs2 = bSrc + (size_t)(it + 1) * 32 * DD;
            CP16(aDst + ab,       as2);
            CP16(aDst + ab + 16,  as2 + 8);
            CP16(bDst + bb,       bs2);
            CP16(bDst + bb + 128, bs2 + 64);
            CP_COMMIT();
            CP_WAIT1();
        } else {
            CP_WAIT0();
        }
        __syncthreads();

        const uint32_t asb = as_b0 + (uint32_t)(it & 1) * (128 * APH * 2);
        const uint32_t bsb = bs_b0 + (uint32_t)(it & 1) * (32 * BPH * 2);
        #pragma unroll
        for (int kc = 0; kc < 2; ++kc) {
            uint32_t af[4][4];
            #pragma unroll
            for (int mt = 0; mt < 4; ++mt)
                ldsm4(af[mt], asb + ((wm + mt * 16 + rA) * APH + kc * 16 + cA) * 2);
            uint32_t bf[2][4];
            ldsm4t(bf[0], bsb + ((kc * 16 + rBt) * BPH + wn + cBt) * 2);
            ldsm4t(bf[1], bsb + ((kc * 16 + rBt) * BPH + wn + 16 + cBt) * 2);
            #pragma unroll
            for (int mt = 0; mt < 4; ++mt) {
                mma_f16(acc[mt][0], af[mt], bf[0][0], bf[0][1]);
                mma_f16(acc[mt][1], af[mt], bf[0][2], bf[0][3]);
                mma_f16(acc[mt][2], af[mt], bf[1][0], bf[1][1]);
                mma_f16(acc[mt][3], af[mt], bf[1][2], bf[1][3]);
            }
        }
        __syncthreads();
    }

    #pragma unroll
    for (int mt = 0; mt < 4; ++mt) {
        #pragma unroll
        for (int nt = 0; nt < 4; ++nt) {
            const int col = n0 + wn + nt * 8 + 2 * tig;
            #pragma unroll
            for (int rh = 0; rh < 2; ++rh) {
                const int m = m0 + wm + mt * 16 + g + rh * 8;
                float2 v = make_float2(acc[mt][nt][rh * 2], acc[mt][nt][rh * 2 + 1]);
                *reinterpret_cast<float2*>(&out[(size_t)m * DD + col]) = v;
            }
        }
    }
}

// ---------------------------------------------------------------------------
// Flash attention: register-resident P + cp.async double-buffered K/V.
// CTA = 128 q-rows; 256 threads / 8 warps (16 q-rows each); 64-key tiles.
// smem: KV[4][64*FPH] — K bufs 0/1, V bufs 0/1; Q staged across K bufs first.
// ---------------------------------------------------------------------------
#define FPH 72
#define NTILE (SS / 64)

__global__ __launch_bounds__(256, 2) void flash_attn_t()
{
    __shared__ __align__(16) __half KV[4 * 64 * FPH];

    const int tid  = threadIdx.x;
    const int w    = tid >> 5;
    const int lane = tid & 31;
    const int g    = lane >> 2;
    const int tig  = lane & 3;
    const int wr   = w * 16;

    const uint32_t kv_b = smem_u32(KV);
    const int rA  = (lane & 7) + ((lane >> 3) & 1) * 8;
    const int cA  = ((lane >> 4) & 1) * 8;
    const int rBn = ((lane >> 4) & 1) * 8 + (lane & 7);
    const int cBn = ((lane >> 3) & 1) * 8;
    const int rBt = (lane & 7) + ((lane >> 3) & 1) * 8;
    const int cBt = ((lane >> 4) & 1) * 8;

    const int q0 = blockIdx.x * 128;
    const int bh = blockIdx.y;
    const __half* Qp = g_Q + (size_t)bh * SS * DK;
    const __half* Kp = g_K + (size_t)bh * SS * DK;
    const __half* Vp = g_V + (size_t)bh * SS * DK;

    // ---- stage Q (rows 0..127 across K-buf space), read qf, then release ----
    {
        const int qr = tid >> 1;
        const int qc = (tid & 1) * 32;
        const uint4* src = reinterpret_cast<const uint4*>(Qp + (size_t)(q0 + qr) * DK + qc);
        #pragma unroll
        for (int j = 0; j < 4; ++j)
            *reinterpret_cast<uint4*>(&KV[qr * FPH + qc + 8 * j]) = src[j];
    }
    __syncthreads();

    uint32_t qf[4][4];
    #pragma unroll
    for (int kc = 0; kc < 4; ++kc)
        ldsm4(qf[kc], kv_b + ((wr + rA) * FPH + kc * 16 + cA) * 2);
    __syncthreads();   // qf read complete before prefetch overwrites

    float of[8][4];
    #pragma unroll
    for (int nt = 0; nt < 8; ++nt)
        #pragma unroll
        for (int i = 0; i < 4; ++i) of[nt][i] = 0.f;
    float mA = -1e30f, mB = -1e30f, lA = 0.f, lB = 0.f;

    // loader: s = tid>>2 (0..63), 16-half chunk at (tid&3)*16
    const int ls = tid >> 2;
    const int lc = (tid & 3) * 16;
    const uint32_t kDst = kv_b + (ls * FPH + lc) * 2;                   // + buf*64*FPH*2
    const uint32_t vDst = kv_b + (2 * 64 * FPH + ls * FPH + lc) * 2;
    const __half* kSrc = Kp + (size_t)ls * DK + lc;
    const __half* vSrc = Vp + (size_t)ls * DK + lc;

    // prefetch tile 0 -> buf 0
    CP16(kDst,      kSrc);
    CP16(kDst + 16, kSrc + 8);
    CP16(vDst,      vSrc);
    CP16(vDst + 16, vSrc + 8);
    CP_COMMIT();

    for (int it = 0; it < NTILE; ++it) {
        if (it + 1 < NTILE) {
            const uint32_t bo = (uint32_t)((it + 1) & 1) * (64 * FPH * 2);
            const __half* ks2 = kSrc + (size_t)(it + 1) * 64 * DK;
            const __half* vs2 = vSrc + (size_t)(it + 1) * 64 * DK;
            CP16(kDst + bo,      ks2);
            CP16(kDst + bo + 16, ks2 + 8);
            CP16(vDst + bo,      vs2);
            CP16(vDst + bo + 16, vs2 + 8);
            CP_COMMIT();
            CP_WAIT1();
        } else {
            CP_WAIT0();
        }
        __syncthreads();

        const uint32_t ksb = kv_b + (uint32_t)(it & 1) * (64 * FPH * 2);
        const uint32_t vsb = ksb + (2 * 64 * FPH * 2);

        // ---- S = Q K^T ----
        float sf[8][4];
        #pragma unroll
        for (int nt = 0; nt < 8; ++nt)
            #pragma unroll
            for (int i = 0; i < 4; ++i) sf[nt][i] = 0.f;
        #pragma unroll
        for (int kc = 0; kc < 4; ++kc) {
            #pragma unroll
            for (int ntp = 0; ntp < 4; ++ntp) {
                uint32_t bf[4];
                ldsm4(bf, ksb + ((ntp * 16 + rBn) * FPH + kc * 16 + cBn) * 2);
                mma_f16(sf[2 * ntp + 0], qf[kc], bf[0], bf[1]);
                mma_f16(sf[2 * ntp + 1], qf[kc], bf[2], bf[3]);
            }
        }

        // ---- online softmax (rows wr+g, wr+g+8), base-2 ----
        float mtA = sf[0][0], mtB = sf[0][2];
        #pragma unroll
        for (int nt = 0; nt < 8; ++nt) {
            mtA = fmaxf(mtA, fmaxf(sf[nt][0], sf[nt][1]));
            mtB = fmaxf(mtB, fmaxf(sf[nt][2], sf[nt][3]));
        }
        mtA = fmaxf(mtA, __shfl_xor_sync(0xffffffffu, mtA, 1));
        mtA = fmaxf(mtA, __shfl_xor_sync(0xffffffffu, mtA, 2));
        mtB = fmaxf(mtB, __shfl_xor_sync(0xffffffffu, mtB, 1));
        mtB = fmaxf(mtB, __shfl_xor_sync(0xffffffffu, mtB, 2));

        const float mnA = fmaxf(mA, mtA);
        const float mnB = fmaxf(mB, mtB);
        const float corA = fast_ex2(mA - mnA);
        const float corB = fast_ex2(mB - mnB);

        float sumA = 0.f, sumB = 0.f;
        #pragma unroll
        for (int nt = 0; nt < 8; ++nt) {
            sf[nt][0] = fast_ex2(sf[nt][0] - mnA);
            sf[nt][1] = fast_ex2(sf[nt][1] - mnA);
            sf[nt][2] = fast_ex2(sf[nt][2] - mnB);
            sf[nt][3] = fast_ex2(sf[nt][3] - mnB);
            sumA += sf[nt][0] + sf[nt][1];
            sumB += sf[nt][2] + sf[nt][3];
        }
        sumA += __shfl_xor_sync(0xffffffffu, sumA, 1);
        sumA += __shfl_xor_sync(0xffffffffu, sumA, 2);
        sumB += __shfl_xor_sync(0xffffffffu, sumB, 1);
        sumB += __shfl_xor_sync(0xffffffffu, sumB, 2);

        lA = lA * corA + sumA; mA = mnA;
        lB = lB * corB + sumB; mB = mnB;
        #pragma unroll
        for (int nt = 0; nt < 8; ++nt) {
            of[nt][0] *= corA; of[nt][1] *= corA;
            of[nt][2] *= corB; of[nt][3] *= corB;
        }

        // ---- P: register repack (S-acc layout == A-frag layout) ----
        uint32_t pf[4][4];
        #pragma unroll
        for (int kc = 0; kc < 4; ++kc) {
            pf[kc][0] = h2pack(sf[2 * kc][0],     sf[2 * kc][1]);
            pf[kc][1] = h2pack(sf[2 * kc][2],     sf[2 * kc][3]);
            pf[kc][2] = h2pack(sf[2 * kc + 1][0], sf[2 * kc + 1][1]);
            pf[kc][3] = h2pack(sf[2 * kc + 1][2], sf[2 * kc + 1][3]);
        }

        // ---- O += P V ----
        #pragma unroll
        for (int kc = 0; kc < 4; ++kc) {
            #pragma unroll
            for (int ntp = 0; ntp < 4; ++ntp) {
                uint32_t bf[4];
                ldsm4t(bf, vsb + ((kc * 16 + rBt) * FPH + ntp * 16 + cBt) * 2);
                mma_f16(of[2 * ntp + 0], pf[kc], bf[0], bf[1]);
                mma_f16(of[2 * ntp + 1], pf[kc], bf[2], bf[3]);
            }
        }
        __syncthreads();
    }

    // ---- epilogue ----
    {
        const float invA = 1.f / lA;
        const float invB = 1.f / lB;
        const int b = bh >> 4, h = bh & 15;
        const size_t rowA = (size_t)b * SS + q0 + wr + g;
        const size_t rowB = rowA + 8;
        #pragma unroll
        for (int nt = 0; nt < 8; ++nt) {
            const int col = h * 64 + nt * 8 + 2 * tig;
            *reinterpret_cast<uint32_t*>(&g_Ct[rowA * DD + col]) =
                h2pack(of[nt][0] * invA, of[nt][1] * invA);
            *reinterpret_cast<uint32_t*>(&g_Ct[rowB * DD + col]) =
                h2pack(of[nt][2] * invB, of[nt][3] * invB);
        }
    }
}

extern "C" void kernel_launch(void* const* d_in, const int* in_sizes, int n_in,
                              void* d_out, int out_size)
{
    const float* x  = (const float*)d_in[0];
    const float* Wq = (const float*)d_in[1];
    const float* Wk = (const float*)d_in[2];
    const float* Wv = (const float*)d_in[3];
    const float* Wo = (const float*)d_in[4];
    float* out = (float*)d_out;

    (void)in_sizes; (void)n_in; (void)out_size;

    conv_x<<<(M_TOT * DD) / (256 * 8), 256>>>(x);
    conv_w<<<(4 * DD * DD) / (256 * 2), 256>>>(Wq, Wk, Wv, Wo);
    qkv_gemm_t<<<dim3(M_TOT / 128, 24), 256>>>();
    flash_attn_t<<<dim3(SS / 128, BB * HH), 256>>>();
    out_gemm_t<<<dim3(M_TOT / 128, DD / 128), 256>>>(out);
}